// round 2
// baseline (speedup 1.0000x reference)
#include <cuda_runtime.h>
#include <math.h>

#define B_    8
#define S_    512
#define N_    128
#define DIN   256
#define DOUT  64
#define DHID  128
#define M_TOT (B_*S_*N_)   // 524288 rows

// Scratch (no allocation allowed)
__device__ float d_scores[M_TOT];          // scores -> attn (in place)
__device__ float d_pooled[B_*N_*DIN];      // (b, n, d)
__device__ float d_g[B_*N_*DOUT];          // (b, n, o)

// ---------------------------------------------------------------------------
// Kernel 1: scores[m] = relu(x[m,:] @ W1^T + b1) . w_len
// Tiled SGEMM 128x128x(K=256, BK=32), 256 threads, 8x8 microtile, fused epilogue.
// ---------------------------------------------------------------------------
#define BM 128
#define BK 32

__global__ __launch_bounds__(256, 2)
void scores_kernel(const float* __restrict__ x,
                   const float* __restrict__ W1,
                   const float* __restrict__ b1,
                   const float* __restrict__ wlen) {
    __shared__ float As[BK][BM];
    __shared__ float Bs[BK][DHID];
    __shared__ float red[BM][17];

    const int tid = threadIdx.x;
    const int tx = tid & 15;       // hidden-col group (8 cols each)
    const int ty = tid >> 4;       // row group (8 rows each)
    const long mBase = (long)blockIdx.x * BM;

    float acc[8][8];
#pragma unroll
    for (int i = 0; i < 8; i++)
#pragma unroll
        for (int j = 0; j < 8; j++) acc[i][j] = 0.f;

    for (int k0 = 0; k0 < DIN; k0 += BK) {
        // Load A tile: 128 rows x 32 k (transposed into smem)
#pragma unroll
        for (int l = 0; l < 4; l++) {
            int i = tid + l * 256;          // 0..1023
            int row = i >> 3;
            int kv = i & 7;
            float4 v = __ldg((const float4*)(x + (mBase + row) * DIN + k0 + kv * 4));
            As[kv*4+0][row] = v.x; As[kv*4+1][row] = v.y;
            As[kv*4+2][row] = v.z; As[kv*4+3][row] = v.w;
        }
        // Load B tile: Bs[k][n] = W1[n][k0+k]
#pragma unroll
        for (int l = 0; l < 4; l++) {
            int i = tid + l * 256;
            int n = i >> 3;
            int kv = i & 7;
            float4 v = __ldg((const float4*)(W1 + n * DIN + k0 + kv * 4));
            Bs[kv*4+0][n] = v.x; Bs[kv*4+1][n] = v.y;
            Bs[kv*4+2][n] = v.z; Bs[kv*4+3][n] = v.w;
        }
        __syncthreads();

#pragma unroll
        for (int kk = 0; kk < BK; kk++) {
            float ra[8], rb[8];
#pragma unroll
            for (int i = 0; i < 8; i++) ra[i] = As[kk][ty * 8 + i];
#pragma unroll
            for (int j = 0; j < 8; j++) rb[j] = Bs[kk][tx * 8 + j];
#pragma unroll
            for (int i = 0; i < 8; i++)
#pragma unroll
                for (int j = 0; j < 8; j++) acc[i][j] += ra[i] * rb[j];
        }
        __syncthreads();
    }

    // Fused epilogue: relu(+b1) . wlen over this thread's 8 hidden cols
    float bb[8], ww[8];
#pragma unroll
    for (int j = 0; j < 8; j++) {
        bb[j] = b1[tx * 8 + j];
        ww[j] = wlen[tx * 8 + j];
    }
#pragma unroll
    for (int i = 0; i < 8; i++) {
        float p = 0.f;
#pragma unroll
        for (int j = 0; j < 8; j++) {
            float h = acc[i][j] + bb[j];
            h = h > 0.f ? h : 0.f;
            p += h * ww[j];
        }
        red[ty * 8 + i][tx] = p;
    }
    __syncthreads();
    if (tid < BM) {
        float s = 0.f;
#pragma unroll
        for (int t = 0; t < 16; t++) s += red[tid][t];
        d_scores[mBase + tid] = s;
    }
}

// ---------------------------------------------------------------------------
// Kernel 2: masked softmax over S (axis=1) for each (b, n). In-place on d_scores.
// mask: score *= (s < len) ? 1 : -10
// ---------------------------------------------------------------------------
__global__ __launch_bounds__(256)
void softmax_kernel(const int* __restrict__ seqlen) {
    const int b = blockIdx.x >> 7;
    const int n = blockIdx.x & 127;
    const int len = seqlen[b];
    __shared__ float sv[S_];
    __shared__ float rbuf[8];
    const int tid = threadIdx.x;

    float lmax = -1e30f;
    for (int s = tid; s < S_; s += 256) {
        float v = d_scores[((long)(b * S_ + s)) * N_ + n];
        v *= (s < len) ? 1.0f : -10.0f;
        sv[s] = v;
        lmax = fmaxf(lmax, v);
    }
#pragma unroll
    for (int o = 16; o > 0; o >>= 1)
        lmax = fmaxf(lmax, __shfl_xor_sync(0xffffffffu, lmax, o));
    if ((tid & 31) == 0) rbuf[tid >> 5] = lmax;
    __syncthreads();
    float bmax = rbuf[0];
#pragma unroll
    for (int w = 1; w < 8; w++) bmax = fmaxf(bmax, rbuf[w]);
    __syncthreads();   // protect rbuf reuse

    float lsum = 0.f;
    for (int s = tid; s < S_; s += 256) {
        float e = expf(sv[s] - bmax);
        sv[s] = e;
        lsum += e;
    }
#pragma unroll
    for (int o = 16; o > 0; o >>= 1)
        lsum += __shfl_xor_sync(0xffffffffu, lsum, o);
    if ((tid & 31) == 0) rbuf[tid >> 5] = lsum;
    __syncthreads();
    float bsum = 0.f;
#pragma unroll
    for (int w = 0; w < 8; w++) bsum += rbuf[w];
    const float inv = 1.0f / bsum;

    for (int s = tid; s < S_; s += 256)
        d_scores[((long)(b * S_ + s)) * N_ + n] = sv[s] * inv;
}

// ---------------------------------------------------------------------------
// Kernel 3: pooled[b,n,d] = sum_s attn[b,s,n] * x[b,s,n,d]   (HBM-bound re-read of x)
// Block per (b,n), thread per d.
// ---------------------------------------------------------------------------
__global__ __launch_bounds__(256)
void pooled_kernel(const float* __restrict__ x) {
    const int b = blockIdx.x >> 7;
    const int n = blockIdx.x & 127;
    __shared__ float a[S_];
    for (int s = threadIdx.x; s < S_; s += 256)
        a[s] = d_scores[((long)(b * S_ + s)) * N_ + n];
    __syncthreads();

    const int t = threadIdx.x;
    const float* xp = x + ((long)(b * S_) * N_ + n) * DIN + t;
    float a0 = 0.f, a1 = 0.f, a2 = 0.f, a3 = 0.f;
#pragma unroll 4
    for (int s = 0; s < S_; s += 4) {
        a0 += a[s + 0] * xp[(long)(s + 0) * N_ * DIN];
        a1 += a[s + 1] * xp[(long)(s + 1) * N_ * DIN];
        a2 += a[s + 2] * xp[(long)(s + 2) * N_ * DIN];
        a3 += a[s + 3] * xp[(long)(s + 3) * N_ * DIN];
    }
    d_pooled[(b * N_ + n) * DIN + t] = (a0 + a1) + (a2 + a3);
}

// ---------------------------------------------------------------------------
// Kernel 4: gated readout. 16 pooled rows per block (64 blocks), weights L2-resident.
// att = sigmoid(p@Wa^T+ba); emb = tanh(p@We^T+be); g = (att*emb)@Wf^T+bf
// ---------------------------------------------------------------------------
__global__ __launch_bounds__(256)
void gated_kernel(const float* __restrict__ Wa, const float* __restrict__ ba,
                  const float* __restrict__ We, const float* __restrict__ be,
                  const float* __restrict__ Wf, const float* __restrict__ bf) {
    const int b = blockIdx.x >> 3;
    const int gr = blockIdx.x & 7;
    __shared__ float P[16][DIN];
    __shared__ float AE[16][DIN];
    const int tid = threadIdx.x;

    for (int i = tid; i < 16 * DIN; i += 256) {
        int r = i >> 8;
        int d = i & 255;
        P[r][d] = d_pooled[((b * N_) + gr * 16 + r) * DIN + d];
    }
    __syncthreads();

    const int o = tid;   // 256 output cols
    for (int r = 0; r < 16; r++) {
        float sa = ba[o], se = be[o];
#pragma unroll 4
        for (int d = 0; d < DIN; d++) {
            float p = P[r][d];
            sa += p * Wa[o * DIN + d];
            se += p * We[o * DIN + d];
        }
        float att = 1.0f / (1.0f + expf(-sa));
        float emb = tanhf(se);
        AE[r][o] = att * emb;
    }
    __syncthreads();

    const int o2 = tid & 63;
    const int rg = tid >> 6;   // 4 rows handled concurrently
    for (int rp = 0; rp < 4; rp++) {
        int r = rp * 4 + rg;
        float sg = bf[o2];
#pragma unroll 4
        for (int d = 0; d < DIN; d++) sg += AE[r][d] * Wf[o2 * DIN + d];
        d_g[((b * N_) + gr * 16 + r) * DOUT + o2] = sg;
    }
}

// ---------------------------------------------------------------------------
// Kernel 5: out[b,o] = sum_n g[b,n,o] / N + max_n g[b,n,o]
// ---------------------------------------------------------------------------
__global__ void final_kernel(float* __restrict__ out) {
    const int b = blockIdx.x;
    const int o = threadIdx.x;   // 64 threads
    float s = 0.f, m = -1e30f;
    for (int n = 0; n < N_; n++) {
        float v = d_g[((b * N_) + n) * DOUT + o];
        s += v;
        m = fmaxf(m, v);
    }
    out[b * DOUT + o] = s / (float)N_ + m;
}

// ---------------------------------------------------------------------------
extern "C" void kernel_launch(void* const* d_in, const int* in_sizes, int n_in,
                              void* d_out, int out_size) {
    const float* x      = (const float*)d_in[0];
    const int*   seqlen = (const int*)  d_in[1];
    const float* W1     = (const float*)d_in[2];
    const float* b1     = (const float*)d_in[3];
    const float* wlen   = (const float*)d_in[4];
    const float* Wa     = (const float*)d_in[5];
    const float* ba     = (const float*)d_in[6];
    const float* We     = (const float*)d_in[7];
    const float* be     = (const float*)d_in[8];
    const float* Wf     = (const float*)d_in[9];
    const float* bf     = (const float*)d_in[10];
    float* out = (float*)d_out;

    scores_kernel<<<M_TOT / BM, 256>>>(x, W1, b1, wlen);
    softmax_kernel<<<B_ * N_, 256>>>(seqlen);
    pooled_kernel<<<B_ * N_, 256>>>(x);
    gated_kernel<<<B_ * 8, 256>>>(Wa, ba, We, be, Wf, bf);
    final_kernel<<<B_, 64>>>(out);
}

// round 5
// speedup vs baseline: 1.3569x; 1.3569x over previous
#include <cuda_runtime.h>
#include <cuda_bf16.h>
#include <math.h>
#include <cstdint>

#define B_    8
#define S_    512
#define N_    128
#define DIN   256
#define DOUT  64
#define DHID  128
#define M_TOT (B_*S_*N_)   // 524288 rows
#define NTILE (M_TOT/128)  // 4096 tiles
#define GRID_SC 148

// Scratch (no allocation allowed)
__device__ float d_scores[M_TOT];
__device__ float d_pooled[B_*N_*DIN];
__device__ float d_g[B_*N_*DOUT];

// ===========================================================================
// scores_mma: scores[m] = relu(x[m,:] @ W1^T + b1) . w_len
// bf16 mma.sync (m16n8k16) with 3-term hi/lo split for fp32-class accuracy.
// Persistent CTAs (148), tile = 128 rows x 128 hid x K256 (chunks of 32).
// ===========================================================================
#define KC      32
#define ASTRIDE 40    // bf16 elems per A smem row (32 + 8 pad)
#define WSTRIDE 264   // bf16 elems per W smem row (256 + 8 pad)
#define W_HI_OFF 0
#define W_LO_OFF (128*WSTRIDE*2)                 // 67584
#define A_HI_OFF (2*128*WSTRIDE*2)               // 135168
#define A_LO_OFF (A_HI_OFF + 128*ASTRIDE*2)      // 145408
#define DYN_SMEM (A_LO_OFF + 128*ASTRIDE*2)      // 155648

__device__ __forceinline__ uint32_t smem_u32(const void* p) {
    uint32_t a;
    asm("{ .reg .u64 t; cvta.to.shared.u64 t, %1; cvt.u32.u64 %0, t; }"
        : "=r"(a) : "l"(p));
    return a;
}
__device__ __forceinline__ void ldsm_x4(uint32_t addr, uint32_t* r) {
    asm volatile("ldmatrix.sync.aligned.m8n8.x4.shared.b16 {%0,%1,%2,%3}, [%4];"
                 : "=r"(r[0]), "=r"(r[1]), "=r"(r[2]), "=r"(r[3]) : "r"(addr));
}
__device__ __forceinline__ void mma_bf16(float* c, const uint32_t* a,
                                         const uint32_t* b) {
    asm volatile(
        "mma.sync.aligned.m16n8k16.row.col.f32.bf16.bf16.f32 "
        "{%0,%1,%2,%3}, {%4,%5,%6,%7}, {%8,%9}, {%0,%1,%2,%3};"
        : "+f"(c[0]), "+f"(c[1]), "+f"(c[2]), "+f"(c[3])
        : "r"(a[0]), "r"(a[1]), "r"(a[2]), "r"(a[3]), "r"(b[0]), "r"(b[1]));
}
// pack two floats -> bf16x2 word; return residuals
__device__ __forceinline__ uint32_t pack_hi(float a, float b, float& ra, float& rb) {
    __nv_bfloat16 ha = __float2bfloat16_rn(a);
    __nv_bfloat16 hb = __float2bfloat16_rn(b);
    ra = a - __bfloat162float(ha);
    rb = b - __bfloat162float(hb);
    __nv_bfloat162 p; p.x = ha; p.y = hb;
    return *reinterpret_cast<uint32_t*>(&p);
}
__device__ __forceinline__ uint32_t pack_lo(float ra, float rb) {
    __nv_bfloat162 p; p.x = __float2bfloat16_rn(ra); p.y = __float2bfloat16_rn(rb);
    return *reinterpret_cast<uint32_t*>(&p);
}

__global__ __launch_bounds__(256)
void scores_mma(const float* __restrict__ x, const float* __restrict__ W1,
                const float* __restrict__ b1, const float* __restrict__ wlen) {
    extern __shared__ char dyn[];
    __nv_bfloat16* Whi = (__nv_bfloat16*)(dyn + W_HI_OFF);
    __nv_bfloat16* Wlo = (__nv_bfloat16*)(dyn + W_LO_OFF);
    __nv_bfloat16* Ahi = (__nv_bfloat16*)(dyn + A_HI_OFF);
    __nv_bfloat16* Alo = (__nv_bfloat16*)(dyn + A_LO_OFF);
    __shared__ float sb1[DHID], swl[DHID];
    __shared__ float red[128][2];

    const int tid = threadIdx.x;
    const int lane = tid & 31;
    const int wid = tid >> 5;
    const int warp_m = wid & 3;          // 4 m-warps (32 rows each)
    const int warp_n = wid >> 2;         // 2 n-warps (64 cols each)

    if (tid < DHID) { sb1[tid] = b1[tid]; swl[tid] = wlen[tid]; }

    // ---- Convert W1 (128x256 fp32) to hi/lo bf16 in smem, once per CTA ----
#pragma unroll 4
    for (int i = 0; i < 32; i++) {
        int j = tid + i * 256;            // float4 index over 8192
        int n = j >> 6;
        int k = (j & 63) * 4;
        float4 v = ((const float4*)W1)[j];
        float r0, r1, r2, r3;
        uint32_t h01 = pack_hi(v.x, v.y, r0, r1);
        uint32_t h23 = pack_hi(v.z, v.w, r2, r3);
        int off = n * WSTRIDE + k;
        *(uint32_t*)(Whi + off)     = h01;
        *(uint32_t*)(Whi + off + 2) = h23;
        *(uint32_t*)(Wlo + off)     = pack_lo(r0, r1);
        *(uint32_t*)(Wlo + off + 2) = pack_lo(r2, r3);
    }
    __syncthreads();

    const uint32_t dbase = smem_u32(dyn);
    const uint32_t WhiU = dbase + W_HI_OFF, WloU = dbase + W_LO_OFF;
    const uint32_t AhiU = dbase + A_HI_OFF, AloU = dbase + A_LO_OFF;

    // lane-dependent ldmatrix address components
    const int am = lane & 15;                        // A row-within-16
    const int ak = (lane >> 4) * 8;                  // A k offset 0/8
    const int bn = (lane & 7) + ((lane >> 4) << 3);  // W n-row within-16
    const int bk8 = ((lane >> 3) & 1) * 8;           // W k offset 0/8

    const int arow_t = tid >> 3;    // load row base (0..31)
    const int acol = tid & 7;       // float4 within 32-float chunk

    // preload chunk 0 of first tile
    float4 st[4];
    {
        const float* Ag0 = x + (long)blockIdx.x * 128 * DIN;
#pragma unroll
        for (int p = 0; p < 4; p++)
            st[p] = *(const float4*)(Ag0 + (long)(arow_t + p * 32) * DIN + acol * 4);
    }

    for (long tile = blockIdx.x; tile < NTILE; tile += GRID_SC) {
        float acc[2][8][4];
#pragma unroll
        for (int mt = 0; mt < 2; mt++)
#pragma unroll
            for (int nt = 0; nt < 8; nt++)
#pragma unroll
                for (int e = 0; e < 4; e++) acc[mt][nt][e] = 0.f;

        const float* Ag0 = x + tile * 128 * DIN;

#pragma unroll 1
        for (int c = 0; c < 8; c++) {
            // --- convert & store current chunk (from staged regs) ---
#pragma unroll
            for (int p = 0; p < 4; p++) {
                int row = arow_t + p * 32;
                float r0, r1, r2, r3;
                uint32_t h01 = pack_hi(st[p].x, st[p].y, r0, r1);
                uint32_t h23 = pack_hi(st[p].z, st[p].w, r2, r3);
                int off = row * ASTRIDE + acol * 4;
                *(uint32_t*)(Ahi + off)     = h01;
                *(uint32_t*)(Ahi + off + 2) = h23;
                *(uint32_t*)(Alo + off)     = pack_lo(r0, r1);
                *(uint32_t*)(Alo + off + 2) = pack_lo(r2, r3);
            }
            __syncthreads();

            // --- prefetch next chunk (or next tile's chunk 0) ---
            {
                const float* src;
                bool more;
                if (c < 7) { src = Ag0 + (c + 1) * KC; more = true; }
                else { src = x + (tile + GRID_SC) * 128 * DIN;
                       more = (tile + GRID_SC) < NTILE; }
                if (more) {
#pragma unroll
                    for (int p = 0; p < 4; p++)
                        st[p] = *(const float4*)(src + (long)(arow_t + p * 32) * DIN
                                                 + acol * 4);
                }
            }

            // --- MMA over this K chunk (two k16 steps) ---
#pragma unroll
            for (int ks = 0; ks < 2; ks++) {
                uint32_t ah[2][4], al[2][4];
#pragma unroll
                for (int mt = 0; mt < 2; mt++) {
                    uint32_t ao = (uint32_t)((warp_m * 32 + mt * 16 + am) * ASTRIDE
                                             + ks * 16 + ak) * 2;
                    ldsm_x4(AhiU + ao, ah[mt]);
                    ldsm_x4(AloU + ao, al[mt]);
                }
                uint32_t bh[4][4], bl[4][4];
                const int kk = c * KC + ks * 16;
#pragma unroll
                for (int q = 0; q < 4; q++) {
                    uint32_t bo = (uint32_t)((warp_n * 64 + q * 16 + bn) * WSTRIDE
                                             + kk + bk8) * 2;
                    ldsm_x4(WhiU + bo, bh[q]);   // NON-trans: [n][k] == col-major KxN
                    ldsm_x4(WloU + bo, bl[q]);
                }
#pragma unroll
                for (int mt = 0; mt < 2; mt++)
#pragma unroll
                    for (int q = 0; q < 4; q++) {
                        mma_bf16(acc[mt][2 * q],     ah[mt], &bh[q][0]);
                        mma_bf16(acc[mt][2 * q + 1], ah[mt], &bh[q][2]);
                        mma_bf16(acc[mt][2 * q],     ah[mt], &bl[q][0]);
                        mma_bf16(acc[mt][2 * q + 1], ah[mt], &bl[q][2]);
                        mma_bf16(acc[mt][2 * q],     al[mt], &bh[q][0]);
                        mma_bf16(acc[mt][2 * q + 1], al[mt], &bh[q][2]);
                    }
            }
            __syncthreads();
        }

        // --- fused epilogue: relu(+b1).wlen, reduce over n ---
        float part[2][2] = {{0.f, 0.f}, {0.f, 0.f}};
#pragma unroll
        for (int nt = 0; nt < 8; nt++) {
            int n0 = warp_n * 64 + nt * 8 + (lane & 3) * 2;
            float bb0 = sb1[n0], bb1 = sb1[n0 + 1];
            float w0 = swl[n0], w1 = swl[n0 + 1];
#pragma unroll
            for (int mt = 0; mt < 2; mt++) {
                part[mt][0] += fmaxf(acc[mt][nt][0] + bb0, 0.f) * w0
                             + fmaxf(acc[mt][nt][1] + bb1, 0.f) * w1;
                part[mt][1] += fmaxf(acc[mt][nt][2] + bb0, 0.f) * w0
                             + fmaxf(acc[mt][nt][3] + bb1, 0.f) * w1;
            }
        }
#pragma unroll
        for (int d = 1; d <= 2; d <<= 1)
#pragma unroll
            for (int mt = 0; mt < 2; mt++) {
                part[mt][0] += __shfl_xor_sync(0xffffffffu, part[mt][0], d);
                part[mt][1] += __shfl_xor_sync(0xffffffffu, part[mt][1], d);
            }
        if ((lane & 3) == 0) {
            int g = lane >> 2;
#pragma unroll
            for (int mt = 0; mt < 2; mt++) {
                red[warp_m * 32 + mt * 16 + g][warp_n]     = part[mt][0];
                red[warp_m * 32 + mt * 16 + 8 + g][warp_n] = part[mt][1];
            }
        }
        __syncthreads();
        if (tid < 128)
            d_scores[tile * 128 + tid] = red[tid][0] + red[tid][1];
        __syncthreads();
    }
}

// ---------------------------------------------------------------------------
// Kernel 2: masked softmax over S for each (b, n). In-place.
// ---------------------------------------------------------------------------
__global__ __launch_bounds__(256)
void softmax_kernel(const int* __restrict__ seqlen) {
    const int b = blockIdx.x >> 7;
    const int n = blockIdx.x & 127;
    const int len = seqlen[b];
    __shared__ float sv[S_];
    __shared__ float rbuf[8];
    const int tid = threadIdx.x;

    float lmax = -1e30f;
    for (int s = tid; s < S_; s += 256) {
        float v = d_scores[((long)(b * S_ + s)) * N_ + n];
        v *= (s < len) ? 1.0f : -10.0f;
        sv[s] = v;
        lmax = fmaxf(lmax, v);
    }
#pragma unroll
    for (int o = 16; o > 0; o >>= 1)
        lmax = fmaxf(lmax, __shfl_xor_sync(0xffffffffu, lmax, o));
    if ((tid & 31) == 0) rbuf[tid >> 5] = lmax;
    __syncthreads();
    float bmax = rbuf[0];
#pragma unroll
    for (int w = 1; w < 8; w++) bmax = fmaxf(bmax, rbuf[w]);
    __syncthreads();

    float lsum = 0.f;
    for (int s = tid; s < S_; s += 256) {
        float e = expf(sv[s] - bmax);
        sv[s] = e;
        lsum += e;
    }
#pragma unroll
    for (int o = 16; o > 0; o >>= 1)
        lsum += __shfl_xor_sync(0xffffffffu, lsum, o);
    if ((tid & 31) == 0) rbuf[tid >> 5] = lsum;
    __syncthreads();
    float bsum = 0.f;
#pragma unroll
    for (int w = 0; w < 8; w++) bsum += rbuf[w];
    const float inv = 1.0f / bsum;

    for (int s = tid; s < S_; s += 256)
        d_scores[((long)(b * S_ + s)) * N_ + n] = sv[s] * inv;
}

// ---------------------------------------------------------------------------
// Kernel 3: pooled[b,n,d] = sum_s attn[b,s,n] * x[b,s,n,d]
// ---------------------------------------------------------------------------
__global__ __launch_bounds__(256)
void pooled_kernel(const float* __restrict__ x) {
    const int b = blockIdx.x >> 7;
    const int n = blockIdx.x & 127;
    __shared__ float a[S_];
    for (int s = threadIdx.x; s < S_; s += 256)
        a[s] = d_scores[((long)(b * S_ + s)) * N_ + n];
    __syncthreads();

    const int t = threadIdx.x;
    const float* xp = x + ((long)(b * S_) * N_ + n) * DIN + t;
    float a0 = 0.f, a1 = 0.f, a2 = 0.f, a3 = 0.f;
#pragma unroll 4
    for (int s = 0; s < S_; s += 4) {
        a0 += a[s + 0] * xp[(long)(s + 0) * N_ * DIN];
        a1 += a[s + 1] * xp[(long)(s + 1) * N_ * DIN];
        a2 += a[s + 2] * xp[(long)(s + 2) * N_ * DIN];
        a3 += a[s + 3] * xp[(long)(s + 3) * N_ * DIN];
    }
    d_pooled[(b * N_ + n) * DIN + t] = (a0 + a1) + (a2 + a3);
}

// ---------------------------------------------------------------------------
// Kernel 4: gated readout
// ---------------------------------------------------------------------------
__global__ __launch_bounds__(256)
void gated_kernel(const float* __restrict__ Wa, const float* __restrict__ ba,
                  const float* __restrict__ We, const float* __restrict__ be,
                  const float* __restrict__ Wf, const float* __restrict__ bf) {
    const int b = blockIdx.x >> 3;
    const int gr = blockIdx.x & 7;
    __shared__ float P[16][DIN];
    __shared__ float AE[16][DIN];
    const int tid = threadIdx.x;

    for (int i = tid; i < 16 * DIN; i += 256) {
        int r = i >> 8;
        int d = i & 255;
        P[r][d] = d_pooled[((b * N_) + gr * 16 + r) * DIN + d];
    }
    __syncthreads();

    const int o = tid;
    for (int r = 0; r < 16; r++) {
        float sa = ba[o], se = be[o];
#pragma unroll 4
        for (int d = 0; d < DIN; d++) {
            float p = P[r][d];
            sa += p * Wa[o * DIN + d];
            se += p * We[o * DIN + d];
        }
        float att = 1.0f / (1.0f + expf(-sa));
        float emb = tanhf(se);
        AE[r][o] = att * emb;
    }
    __syncthreads();

    const int o2 = tid & 63;
    const int rg = tid >> 6;
    for (int rp = 0; rp < 4; rp++) {
        int r = rp * 4 + rg;
        float sg = bf[o2];
#pragma unroll 4
        for (int d = 0; d < DIN; d++) sg += AE[r][d] * Wf[o2 * DIN + d];
        d_g[((b * N_) + gr * 16 + r) * DOUT + o2] = sg;
    }
}

// ---------------------------------------------------------------------------
// Kernel 5: out[b,o] = sum_n g[b,n,o] / N + max_n g[b,n,o]
// ---------------------------------------------------------------------------
__global__ void final_kernel(float* __restrict__ out) {
    const int b = blockIdx.x;
    const int o = threadIdx.x;   // 64 threads
    float s = 0.f, m = -1e30f;
    for (int n = 0; n < N_; n++) {
        float v = d_g[((b * N_) + n) * DOUT + o];
        s += v;
        m = fmaxf(m, v);
    }
    out[b * DOUT + o] = s / (float)N_ + m;
}

// ---------------------------------------------------------------------------
extern "C" void kernel_launch(void* const* d_in, const int* in_sizes, int n_in,
                              void* d_out, int out_size) {
    const float* x      = (const float*)d_in[0];
    const int*   seqlen = (const int*)  d_in[1];
    const float* W1     = (const float*)d_in[2];
    const float* b1     = (const float*)d_in[3];
    const float* wlen   = (const float*)d_in[4];
    const float* Wa     = (const float*)d_in[5];
    const float* ba     = (const float*)d_in[6];
    const float* We     = (const float*)d_in[7];
    const float* be     = (const float*)d_in[8];
    const float* Wf     = (const float*)d_in[9];
    const float* bf     = (const float*)d_in[10];
    float* out = (float*)d_out;

    static int smem_set = 0;
    if (!smem_set) {
        cudaFuncSetAttribute(scores_mma,
                             cudaFuncAttributeMaxDynamicSharedMemorySize, DYN_SMEM);
        smem_set = 1;
    }
    scores_mma<<<GRID_SC, 256, DYN_SMEM>>>(x, W1, b1, wlen);
    softmax_kernel<<<B_ * N_, 256>>>(seqlen);
    pooled_kernel<<<B_ * N_, 256>>>(x);
    gated_kernel<<<B_ * 8, 256>>>(Wa, ba, We, be, Wf, bf);
    final_kernel<<<B_, 64>>>(out);
}

// round 7
// speedup vs baseline: 1.4040x; 1.0347x over previous
#include <cuda_runtime.h>
#include <cuda_fp16.h>
#include <math.h>
#include <cstdint>

#define B_    8
#define S_    512
#define N_    128
#define DIN   256
#define DOUT  64
#define DHID  128
#define M_TOT (B_*S_*N_)   // 524288 rows
#define NTILE (M_TOT/128)  // 4096 tiles
#define GRID_SC 148

// Scratch (no allocation allowed)
__device__ float d_scores[M_TOT];
__device__ float d_pooled[B_*N_*DIN];
__device__ float d_g[B_*N_*DOUT];

// ===========================================================================
// scores_mma: scores[m] = relu(x[m,:] @ W1^T + b1) . w_len
// fp16 mma.sync m16n8k16, 2-term split on W (Whi+Wlo), x single fp16.
// 512 threads (16 warps, 4m x 4n), double-buffered A smem, persistent CTAs.
// ===========================================================================
#define KC      32
#define ASTRIDE 40     // fp16 elems per A row (32 + 8 pad)  -> 80 B
#define ASLAB   (128*ASTRIDE*2)   // 10240 B per stage
#define WSTRIDE 264    // fp16 elems per W row (256 + 8 pad) -> 528 B
#define W_HI_OFF 0
#define W_LO_OFF (128*WSTRIDE*2)              // 67584
#define A_OFF    (2*128*WSTRIDE*2)            // 135168
#define DYN_SMEM (A_OFF + 2*ASLAB)            // 155648

__device__ __forceinline__ uint32_t smem_u32(const void* p) {
    uint32_t a;
    asm("{ .reg .u64 t; cvta.to.shared.u64 t, %1; cvt.u32.u64 %0, t; }"
        : "=r"(a) : "l"(p));
    return a;
}
__device__ __forceinline__ void ldsm_x4(uint32_t addr, uint32_t* r) {
    asm volatile("ldmatrix.sync.aligned.m8n8.x4.shared.b16 {%0,%1,%2,%3}, [%4];"
                 : "=r"(r[0]), "=r"(r[1]), "=r"(r[2]), "=r"(r[3]) : "r"(addr));
}
__device__ __forceinline__ void mma_f16(float* c, const uint32_t* a,
                                        const uint32_t* b) {
    asm volatile(
        "mma.sync.aligned.m16n8k16.row.col.f32.f16.f16.f32 "
        "{%0,%1,%2,%3}, {%4,%5,%6,%7}, {%8,%9}, {%0,%1,%2,%3};"
        : "+f"(c[0]), "+f"(c[1]), "+f"(c[2]), "+f"(c[3])
        : "r"(a[0]), "r"(a[1]), "r"(a[2]), "r"(a[3]), "r"(b[0]), "r"(b[1]));
}
__device__ __forceinline__ uint32_t h2bits(__half2 h) {
    return *reinterpret_cast<uint32_t*>(&h);
}

__global__ __launch_bounds__(512)
void scores_mma(const float* __restrict__ x, const float* __restrict__ W1,
                const float* __restrict__ b1, const float* __restrict__ wlen) {
    extern __shared__ char dyn[];
    __shared__ float sb1[DHID], swl[DHID];
    __shared__ float red[128][4];

    const int tid = threadIdx.x;
    const int lane = tid & 31;
    const int wid = tid >> 5;
    const int warp_m = wid & 3;          // 4 m-groups (32 rows)
    const int warp_n = wid >> 2;         // 4 n-groups (32 cols)

    if (tid < DHID) { sb1[tid] = b1[tid]; swl[tid] = wlen[tid]; }

    // ---- Convert W1 (128x256 fp32) to Whi/Wlo fp16 in smem, once ----
    {
        __half* Whi = (__half*)(dyn + W_HI_OFF);
        __half* Wlo = (__half*)(dyn + W_LO_OFF);
#pragma unroll
        for (int it = 0; it < 16; it++) {
            int i = tid + it * 512;          // float4 index over 8192
            int n = i >> 6;
            int k4 = i & 63;
            float4 v = ((const float4*)W1)[i];
            __half hx = __float2half_rn(v.x), hy = __float2half_rn(v.y);
            __half hz = __float2half_rn(v.z), hw = __float2half_rn(v.w);
            float rx = v.x - __half2float(hx), ry = v.y - __half2float(hy);
            float rz = v.z - __half2float(hz), rw = v.w - __half2float(hw);
            int off = n * WSTRIDE + k4 * 4;
            uint2 hi, lo;
            hi.x = h2bits(__halves2half2(hx, hy));
            hi.y = h2bits(__halves2half2(hz, hw));
            lo.x = h2bits(__floats2half2_rn(rx, ry));
            lo.y = h2bits(__floats2half2_rn(rz, rw));
            *(uint2*)(Whi + off) = hi;
            *(uint2*)(Wlo + off) = lo;
        }
    }

    const uint32_t dbase = smem_u32(dyn);
    const uint32_t WhiU = dbase + W_HI_OFF, WloU = dbase + W_LO_OFF;
    const uint32_t AU = dbase + A_OFF;
    char* Abase = dyn + A_OFF;

    // lane-dependent ldmatrix address components
    const int am = lane & 15;                        // A row-within-16
    const int ak = (lane >> 4) * 8;                  // A k offset 0/8
    const int bn = (lane & 7) + ((lane >> 4) << 3);  // W n-row within-16
    const int bk8 = ((lane >> 3) & 1) * 8;           // W k offset 0/8

    const int arow = tid >> 3;       // 0..63; handles rows arow, arow+64
    const int acol = tid & 7;        // float4 within 32-float chunk row

    float4 st[2];
    auto load_st = [&](const float* src) {
        st[0] = *(const float4*)(src + (long)arow * DIN + acol * 4);
        st[1] = *(const float4*)(src + (long)(arow + 64) * DIN + acol * 4);
    };
    auto conv_store = [&](int stage) {
        char* A = Abase + stage * ASLAB;
#pragma unroll
        for (int p = 0; p < 2; p++) {
            int row = arow + p * 64;
            uint2 w;
            w.x = h2bits(__floats2half2_rn(st[p].x, st[p].y));
            w.y = h2bits(__floats2half2_rn(st[p].z, st[p].w));
            *(uint2*)(A + row * 80 + acol * 8) = w;
        }
    };

    // preload chunk 0 of first tile
    load_st(x + (long)blockIdx.x * 128 * DIN);

    for (long tile = blockIdx.x; tile < NTILE; tile += GRID_SC) {
        float acc[2][4][4];
#pragma unroll
        for (int mt = 0; mt < 2; mt++)
#pragma unroll
            for (int j = 0; j < 4; j++)
#pragma unroll
                for (int e = 0; e < 4; e++) acc[mt][j][e] = 0.f;

        const float* Ag0 = x + tile * 128 * DIN;

        conv_store(0);                 // chunk 0 -> stage 0
        load_st(Ag0 + KC);             // chunk 1 -> regs
        __syncthreads();

#pragma unroll 1
        for (int c = 0; c < 8; c++) {
            // store chunk c+1 into the other stage; prefetch chunk c+2
            if (c < 7) {
                conv_store((c + 1) & 1);
                if (c < 6) load_st(Ag0 + (c + 2) * KC);
                else if (tile + GRID_SC < NTILE)
                    load_st(x + (tile + GRID_SC) * 128 * DIN);
            }

            // MMA on stage c&1
            const uint32_t Ast = AU + (uint32_t)(c & 1) * ASLAB;
#pragma unroll
            for (int ks = 0; ks < 2; ks++) {
                uint32_t ah[2][4];
#pragma unroll
                for (int mt = 0; mt < 2; mt++) {
                    uint32_t ao = Ast + (uint32_t)((warp_m * 32 + mt * 16 + am) * 80
                                                   + (ks * 16 + ak) * 2);
                    ldsm_x4(ao, ah[mt]);
                }
                uint32_t bh[2][4], bl[2][4];
                const int kk = c * KC + ks * 16;
#pragma unroll
                for (int q = 0; q < 2; q++) {
                    uint32_t bo = (uint32_t)((warp_n * 32 + q * 16 + bn) * WSTRIDE
                                             + kk + bk8) * 2;
                    ldsm_x4(WhiU + bo, bh[q]);
                    ldsm_x4(WloU + bo, bl[q]);
                }
#pragma unroll
                for (int mt = 0; mt < 2; mt++)
#pragma unroll
                    for (int q = 0; q < 2; q++) {
                        mma_f16(acc[mt][2 * q],     ah[mt], &bh[q][0]);
                        mma_f16(acc[mt][2 * q],     ah[mt], &bl[q][0]);
                        mma_f16(acc[mt][2 * q + 1], ah[mt], &bh[q][2]);
                        mma_f16(acc[mt][2 * q + 1], ah[mt], &bl[q][2]);
                    }
            }
            __syncthreads();
        }

        // --- fused epilogue: relu(+b1).wlen, reduce over n ---
        float part[2][2] = {{0.f, 0.f}, {0.f, 0.f}};
#pragma unroll
        for (int j = 0; j < 4; j++) {
            int n0 = warp_n * 32 + j * 8 + (lane & 3) * 2;
            float bb0 = sb1[n0], bb1 = sb1[n0 + 1];
            float w0 = swl[n0], w1 = swl[n0 + 1];
#pragma unroll
            for (int mt = 0; mt < 2; mt++) {
                part[mt][0] += fmaxf(acc[mt][j][0] + bb0, 0.f) * w0
                             + fmaxf(acc[mt][j][1] + bb1, 0.f) * w1;
                part[mt][1] += fmaxf(acc[mt][j][2] + bb0, 0.f) * w0
                             + fmaxf(acc[mt][j][3] + bb1, 0.f) * w1;
            }
        }
#pragma unroll
        for (int d = 1; d <= 2; d <<= 1)
#pragma unroll
            for (int mt = 0; mt < 2; mt++) {
                part[mt][0] += __shfl_xor_sync(0xffffffffu, part[mt][0], d);
                part[mt][1] += __shfl_xor_sync(0xffffffffu, part[mt][1], d);
            }
        if ((lane & 3) == 0) {
            int g = lane >> 2;
#pragma unroll
            for (int mt = 0; mt < 2; mt++) {
                red[warp_m * 32 + mt * 16 + g][warp_n]     = part[mt][0];
                red[warp_m * 32 + mt * 16 + 8 + g][warp_n] = part[mt][1];
            }
        }
        __syncthreads();
        if (tid < 128)
            d_scores[tile * 128 + tid] = red[tid][0] + red[tid][1]
                                       + red[tid][2] + red[tid][3];
        __syncthreads();
    }
}

// ---------------------------------------------------------------------------
// Kernel 2: masked softmax over S for each (b, n). In-place.
// ---------------------------------------------------------------------------
__global__ __launch_bounds__(256)
void softmax_kernel(const int* __restrict__ seqlen) {
    const int b = blockIdx.x >> 7;
    const int n = blockIdx.x & 127;
    const int len = seqlen[b];
    __shared__ float sv[S_];
    __shared__ float rbuf[8];
    const int tid = threadIdx.x;

    float lmax = -1e30f;
    for (int s = tid; s < S_; s += 256) {
        float v = d_scores[((long)(b * S_ + s)) * N_ + n];
        v *= (s < len) ? 1.0f : -10.0f;
        sv[s] = v;
        lmax = fmaxf(lmax, v);
    }
#pragma unroll
    for (int o = 16; o > 0; o >>= 1)
        lmax = fmaxf(lmax, __shfl_xor_sync(0xffffffffu, lmax, o));
    if ((tid & 31) == 0) rbuf[tid >> 5] = lmax;
    __syncthreads();
    float bmax = rbuf[0];
#pragma unroll
    for (int w = 1; w < 8; w++) bmax = fmaxf(bmax, rbuf[w]);
    __syncthreads();

    float lsum = 0.f;
    for (int s = tid; s < S_; s += 256) {
        float e = expf(sv[s] - bmax);
        sv[s] = e;
        lsum += e;
    }
#pragma unroll
    for (int o = 16; o > 0; o >>= 1)
        lsum += __shfl_xor_sync(0xffffffffu, lsum, o);
    if ((tid & 31) == 0) rbuf[tid >> 5] = lsum;
    __syncthreads();
    float bsum = 0.f;
#pragma unroll
    for (int w = 0; w < 8; w++) bsum += rbuf[w];
    const float inv = 1.0f / bsum;

    for (int s = tid; s < S_; s += 256)
        d_scores[((long)(b * S_ + s)) * N_ + n] = sv[s] * inv;
}

// ---------------------------------------------------------------------------
// Kernel 3: pooled[b,n,d] = sum_s attn[b,s,n] * x[b,s,n,d]
// ---------------------------------------------------------------------------
__global__ __launch_bounds__(256)
void pooled_kernel(const float* __restrict__ x) {
    const int b = blockIdx.x >> 7;
    const int n = blockIdx.x & 127;
    __shared__ float a[S_];
    for (int s = threadIdx.x; s < S_; s += 256)
        a[s] = d_scores[((long)(b * S_ + s)) * N_ + n];
    __syncthreads();

    const int t = threadIdx.x;
    const float* xp = x + ((long)(b * S_) * N_ + n) * DIN + t;
    float a0 = 0.f, a1 = 0.f, a2 = 0.f, a3 = 0.f;
#pragma unroll 4
    for (int s = 0; s < S_; s += 4) {
        a0 += a[s + 0] * xp[(long)(s + 0) * N_ * DIN];
        a1 += a[s + 1] * xp[(long)(s + 1) * N_ * DIN];
        a2 += a[s + 2] * xp[(long)(s + 2) * N_ * DIN];
        a3 += a[s + 3] * xp[(long)(s + 3) * N_ * DIN];
    }
    d_pooled[(b * N_ + n) * DIN + t] = (a0 + a1) + (a2 + a3);
}

// ---------------------------------------------------------------------------
// Kernel 4: gated readout
// ---------------------------------------------------------------------------
__global__ __launch_bounds__(256)
void gated_kernel(const float* __restrict__ Wa, const float* __restrict__ ba,
                  const float* __restrict__ We, const float* __restrict__ be,
                  const float* __restrict__ Wf, const float* __restrict__ bf) {
    const int b = blockIdx.x >> 3;
    const int gr = blockIdx.x & 7;
    __shared__ float P[16][DIN];
    __shared__ float AE[16][DIN];
    const int tid = threadIdx.x;

    for (int i = tid; i < 16 * DIN; i += 256) {
        int r = i >> 8;
        int d = i & 255;
        P[r][d] = d_pooled[((b * N_) + gr * 16 + r) * DIN + d];
    }
    __syncthreads();

    const int o = tid;
    for (int r = 0; r < 16; r++) {
        float sa = ba[o], se = be[o];
#pragma unroll 4
        for (int d = 0; d < DIN; d++) {
            float p = P[r][d];
            sa += p * Wa[o * DIN + d];
            se += p * We[o * DIN + d];
        }
        float att = 1.0f / (1.0f + expf(-sa));
        float emb = tanhf(se);
        AE[r][o] = att * emb;
    }
    __syncthreads();

    const int o2 = tid & 63;
    const int rg = tid >> 6;
    for (int rp = 0; rp < 4; rp++) {
        int r = rp * 4 + rg;
        float sg = bf[o2];
#pragma unroll 4
        for (int d = 0; d < DIN; d++) sg += AE[r][d] * Wf[o2 * DIN + d];
        d_g[((b * N_) + gr * 16 + r) * DOUT + o2] = sg;
    }
}

// ---------------------------------------------------------------------------
// Kernel 5: out[b,o] = sum_n g[b,n,o] / N + max_n g[b,n,o]
// ---------------------------------------------------------------------------
__global__ void final_kernel(float* __restrict__ out) {
    const int b = blockIdx.x;
    const int o = threadIdx.x;   // 64 threads
    float s = 0.f, m = -1e30f;
    for (int n = 0; n < N_; n++) {
        float v = d_g[((b * N_) + n) * DOUT + o];
        s += v;
        m = fmaxf(m, v);
    }
    out[b * DOUT + o] = s / (float)N_ + m;
}

// ---------------------------------------------------------------------------
extern "C" void kernel_launch(void* const* d_in, const int* in_sizes, int n_in,
                              void* d_out, int out_size) {
    const float* x      = (const float*)d_in[0];
    const int*   seqlen = (const int*)  d_in[1];
    const float* W1     = (const float*)d_in[2];
    const float* b1     = (const float*)d_in[3];
    const float* wlen   = (const float*)d_in[4];
    const float* Wa     = (const float*)d_in[5];
    const float* ba     = (const float*)d_in[6];
    const float* We     = (const float*)d_in[7];
    const float* be     = (const float*)d_in[8];
    const float* Wf     = (const float*)d_in[9];
    const float* bf     = (const float*)d_in[10];
    float* out = (float*)d_out;

    static int smem_set = 0;
    if (!smem_set) {
        cudaFuncSetAttribute(scores_mma,
                             cudaFuncAttributeMaxDynamicSharedMemorySize, DYN_SMEM);
        smem_set = 1;
    }
    scores_mma<<<GRID_SC, 512, DYN_SMEM>>>(x, W1, b1, wlen);
    softmax_kernel<<<B_ * N_, 256>>>(seqlen);
    pooled_kernel<<<B_ * N_, 256>>>(x);
    gated_kernel<<<B_ * 8, 256>>>(Wa, ba, We, be, Wf, bf);
    final_kernel<<<B_, 64>>>(out);
}

// round 8
// speedup vs baseline: 1.4232x; 1.0136x over previous
#include <cuda_runtime.h>
#include <cuda_fp16.h>
#include <math.h>
#include <cstdint>

#define B_    8
#define S_    512
#define N_    128
#define DIN   256
#define DOUT  64
#define DHID  128
#define M_TOT (B_*S_*N_)   // 524288 rows
#define NTILE (M_TOT/128)  // 4096 tiles
#define GRID_SC 148

// Scratch (no allocation allowed). d_scores layout: (b, n, s) transposed!
__device__ float d_scores[M_TOT];
__device__ float d_pooled[B_*N_*DIN];
__device__ float d_g[B_*N_*DOUT];

// ===========================================================================
// scores_mma: masked_score[b,n,s] = (relu(x @ W1^T + b1) . w_len) * mask(b,s)
// fp16 mma.sync m16n8k16, 2-term split on W. 512 threads, double-buffered A.
// ===========================================================================
#define KC      32
#define ASTRIDE 40
#define ASLAB   (128*ASTRIDE*2)
#define WSTRIDE 264
#define W_HI_OFF 0
#define W_LO_OFF (128*WSTRIDE*2)
#define A_OFF    (2*128*WSTRIDE*2)
#define DYN_SMEM (A_OFF + 2*ASLAB)

__device__ __forceinline__ uint32_t smem_u32(const void* p) {
    uint32_t a;
    asm("{ .reg .u64 t; cvta.to.shared.u64 t, %1; cvt.u32.u64 %0, t; }"
        : "=r"(a) : "l"(p));
    return a;
}
__device__ __forceinline__ void ldsm_x4(uint32_t addr, uint32_t* r) {
    asm volatile("ldmatrix.sync.aligned.m8n8.x4.shared.b16 {%0,%1,%2,%3}, [%4];"
                 : "=r"(r[0]), "=r"(r[1]), "=r"(r[2]), "=r"(r[3]) : "r"(addr));
}
__device__ __forceinline__ void mma_f16(float* c, const uint32_t* a,
                                        const uint32_t* b) {
    asm volatile(
        "mma.sync.aligned.m16n8k16.row.col.f32.f16.f16.f32 "
        "{%0,%1,%2,%3}, {%4,%5,%6,%7}, {%8,%9}, {%0,%1,%2,%3};"
        : "+f"(c[0]), "+f"(c[1]), "+f"(c[2]), "+f"(c[3])
        : "r"(a[0]), "r"(a[1]), "r"(a[2]), "r"(a[3]), "r"(b[0]), "r"(b[1]));
}
__device__ __forceinline__ uint32_t h2bits(__half2 h) {
    return *reinterpret_cast<uint32_t*>(&h);
}

__global__ __launch_bounds__(512)
void scores_mma(const float* __restrict__ x, const float* __restrict__ W1,
                const float* __restrict__ b1, const float* __restrict__ wlen,
                const int* __restrict__ seqlen) {
    extern __shared__ char dyn[];
    __shared__ float sb1[DHID], swl[DHID];
    __shared__ float red[128][4];

    const int tid = threadIdx.x;
    const int lane = tid & 31;
    const int wid = tid >> 5;
    const int warp_m = wid & 3;
    const int warp_n = wid >> 2;

    if (tid < DHID) { sb1[tid] = b1[tid]; swl[tid] = wlen[tid]; }

    // ---- W1 -> Whi/Wlo fp16 smem ----
    {
        __half* Whi = (__half*)(dyn + W_HI_OFF);
        __half* Wlo = (__half*)(dyn + W_LO_OFF);
#pragma unroll
        for (int it = 0; it < 16; it++) {
            int i = tid + it * 512;
            int n = i >> 6;
            int k4 = i & 63;
            float4 v = ((const float4*)W1)[i];
            __half hx = __float2half_rn(v.x), hy = __float2half_rn(v.y);
            __half hz = __float2half_rn(v.z), hw = __float2half_rn(v.w);
            float rx = v.x - __half2float(hx), ry = v.y - __half2float(hy);
            float rz = v.z - __half2float(hz), rw = v.w - __half2float(hw);
            int off = n * WSTRIDE + k4 * 4;
            uint2 hi, lo;
            hi.x = h2bits(__halves2half2(hx, hy));
            hi.y = h2bits(__halves2half2(hz, hw));
            lo.x = h2bits(__floats2half2_rn(rx, ry));
            lo.y = h2bits(__floats2half2_rn(rz, rw));
            *(uint2*)(Whi + off) = hi;
            *(uint2*)(Wlo + off) = lo;
        }
    }

    const uint32_t dbase = smem_u32(dyn);
    const uint32_t WhiU = dbase + W_HI_OFF, WloU = dbase + W_LO_OFF;
    const uint32_t AU = dbase + A_OFF;
    char* Abase = dyn + A_OFF;

    const int am = lane & 15;
    const int ak = (lane >> 4) * 8;
    const int bn = (lane & 7) + ((lane >> 4) << 3);
    const int bk8 = ((lane >> 3) & 1) * 8;

    const int arow = tid >> 3;
    const int acol = tid & 7;

    float4 st[2];
    auto load_st = [&](const float* src) {
        st[0] = *(const float4*)(src + (long)arow * DIN + acol * 4);
        st[1] = *(const float4*)(src + (long)(arow + 64) * DIN + acol * 4);
    };
    auto conv_store = [&](int stage) {
        char* A = Abase + stage * ASLAB;
#pragma unroll
        for (int p = 0; p < 2; p++) {
            int row = arow + p * 64;
            uint2 w;
            w.x = h2bits(__floats2half2_rn(st[p].x, st[p].y));
            w.y = h2bits(__floats2half2_rn(st[p].z, st[p].w));
            *(uint2*)(A + row * 80 + acol * 8) = w;
        }
    };

    load_st(x + (long)blockIdx.x * 128 * DIN);

    for (long tile = blockIdx.x; tile < NTILE; tile += GRID_SC) {
        float acc[2][4][4];
#pragma unroll
        for (int mt = 0; mt < 2; mt++)
#pragma unroll
            for (int j = 0; j < 4; j++)
#pragma unroll
                for (int e = 0; e < 4; e++) acc[mt][j][e] = 0.f;

        const float* Ag0 = x + tile * 128 * DIN;

        conv_store(0);
        load_st(Ag0 + KC);
        __syncthreads();

#pragma unroll 1
        for (int c = 0; c < 8; c++) {
            if (c < 7) {
                conv_store((c + 1) & 1);
                if (c < 6) load_st(Ag0 + (c + 2) * KC);
                else if (tile + GRID_SC < NTILE)
                    load_st(x + (tile + GRID_SC) * 128 * DIN);
            }

            const uint32_t Ast = AU + (uint32_t)(c & 1) * ASLAB;
#pragma unroll
            for (int ks = 0; ks < 2; ks++) {
                uint32_t ah[2][4];
#pragma unroll
                for (int mt = 0; mt < 2; mt++) {
                    uint32_t ao = Ast + (uint32_t)((warp_m * 32 + mt * 16 + am) * 80
                                                   + (ks * 16 + ak) * 2);
                    ldsm_x4(ao, ah[mt]);
                }
                uint32_t bh[2][4], bl[2][4];
                const int kk = c * KC + ks * 16;
#pragma unroll
                for (int q = 0; q < 2; q++) {
                    uint32_t bo = (uint32_t)((warp_n * 32 + q * 16 + bn) * WSTRIDE
                                             + kk + bk8) * 2;
                    ldsm_x4(WhiU + bo, bh[q]);
                    ldsm_x4(WloU + bo, bl[q]);
                }
#pragma unroll
                for (int mt = 0; mt < 2; mt++)
#pragma unroll
                    for (int q = 0; q < 2; q++) {
                        mma_f16(acc[mt][2 * q],     ah[mt], &bh[q][0]);
                        mma_f16(acc[mt][2 * q],     ah[mt], &bl[q][0]);
                        mma_f16(acc[mt][2 * q + 1], ah[mt], &bh[q][2]);
                        mma_f16(acc[mt][2 * q + 1], ah[mt], &bl[q][2]);
                    }
            }
            __syncthreads();
        }

        // --- epilogue: relu(+b1).wlen, reduce over n-groups ---
        float part[2][2] = {{0.f, 0.f}, {0.f, 0.f}};
#pragma unroll
        for (int j = 0; j < 4; j++) {
            int n0 = warp_n * 32 + j * 8 + (lane & 3) * 2;
            float bb0 = sb1[n0], bb1 = sb1[n0 + 1];
            float w0 = swl[n0], w1 = swl[n0 + 1];
#pragma unroll
            for (int mt = 0; mt < 2; mt++) {
                part[mt][0] += fmaxf(acc[mt][j][0] + bb0, 0.f) * w0
                             + fmaxf(acc[mt][j][1] + bb1, 0.f) * w1;
                part[mt][1] += fmaxf(acc[mt][j][2] + bb0, 0.f) * w0
                             + fmaxf(acc[mt][j][3] + bb1, 0.f) * w1;
            }
        }
#pragma unroll
        for (int d = 1; d <= 2; d <<= 1)
#pragma unroll
            for (int mt = 0; mt < 2; mt++) {
                part[mt][0] += __shfl_xor_sync(0xffffffffu, part[mt][0], d);
                part[mt][1] += __shfl_xor_sync(0xffffffffu, part[mt][1], d);
            }
        if ((lane & 3) == 0) {
            int g = lane >> 2;
#pragma unroll
            for (int mt = 0; mt < 2; mt++) {
                red[warp_m * 32 + mt * 16 + g][warp_n]     = part[mt][0];
                red[warp_m * 32 + mt * 16 + 8 + g][warp_n] = part[mt][1];
            }
        }
        __syncthreads();
        // tile => fixed (b, s); tid (=n) scatters into (b, n, s) layout, masked.
        if (tid < 128) {
            const int b = (int)(tile / S_);
            const int s = (int)(tile % S_);
            float sc = red[tid][0] + red[tid][1] + red[tid][2] + red[tid][3];
            sc *= (s < seqlen[b]) ? 1.0f : -10.0f;
            d_scores[((long)b * N_ + tid) * S_ + s] = sc;
        }
        __syncthreads();
    }
}

// ---------------------------------------------------------------------------
// Kernel 2: softmax over contiguous s rows. Warp per (b,n) row, all in regs.
// ---------------------------------------------------------------------------
__global__ __launch_bounds__(256)
void softmax_kernel() {
    const int row = blockIdx.x * 8 + (threadIdx.x >> 5);   // (b*N + n), 0..1023
    const int lane = threadIdx.x & 31;
    float* base = d_scores + (long)row * S_;

    float v[16];
    float lmax = -1e30f;
#pragma unroll
    for (int i = 0; i < 16; i++) {
        v[i] = base[lane + i * 32];
        lmax = fmaxf(lmax, v[i]);
    }
#pragma unroll
    for (int o = 16; o > 0; o >>= 1)
        lmax = fmaxf(lmax, __shfl_xor_sync(0xffffffffu, lmax, o));
    float lsum = 0.f;
#pragma unroll
    for (int i = 0; i < 16; i++) {
        v[i] = expf(v[i] - lmax);
        lsum += v[i];
    }
#pragma unroll
    for (int o = 16; o > 0; o >>= 1)
        lsum += __shfl_xor_sync(0xffffffffu, lsum, o);
    const float inv = 1.0f / lsum;
#pragma unroll
    for (int i = 0; i < 16; i++)
        base[lane + i * 32] = v[i] * inv;
}

// ---------------------------------------------------------------------------
// Kernel 3: pooled[b,n,d] = sum_s attn[b,n,s] * x[b,s,n,d]
// 512 threads: 4 s-groups x 128 float2-lanes. smem tree-reduce.
// ---------------------------------------------------------------------------
__global__ __launch_bounds__(512)
void pooled_kernel(const float* __restrict__ x) {
    const int b = blockIdx.x >> 7;
    const int n = blockIdx.x & 127;
    __shared__ float a[S_];
    __shared__ float2 part[4][128];

    const int tid = threadIdx.x;
    a[tid] = d_scores[((long)(b * N_ + n)) * S_ + tid];   // contiguous attn row
    __syncthreads();

    const int sq = tid >> 7;          // 0..3 : s quarter
    const int dh = tid & 127;         // float2 index over DIN
    const float2* xp = (const float2*)(x + ((long)(b * S_ + sq * 128) * N_ + n) * DIN)
                       + dh;
    const float* aq = a + sq * 128;
    const long stride2 = (long)N_ * DIN / 2;   // float2 stride per s

    float2 accv = make_float2(0.f, 0.f);
#pragma unroll 8
    for (int s = 0; s < 128; s++) {
        float w = aq[s];
        float2 v = xp[(long)s * stride2];
        accv.x += w * v.x;
        accv.y += w * v.y;
    }
    part[sq][dh] = accv;
    __syncthreads();
    if (tid < 128) {
        float2 p0 = part[0][tid], p1 = part[1][tid];
        float2 p2 = part[2][tid], p3 = part[3][tid];
        float2 r;
        r.x = (p0.x + p1.x) + (p2.x + p3.x);
        r.y = (p0.y + p1.y) + (p2.y + p3.y);
        ((float2*)(d_pooled + ((long)(b * N_ + n)) * DIN))[tid] = r;
    }
}

// ---------------------------------------------------------------------------
// Kernel 4: gated readout
// ---------------------------------------------------------------------------
__global__ __launch_bounds__(256)
void gated_kernel(const float* __restrict__ Wa, const float* __restrict__ ba,
                  const float* __restrict__ We, const float* __restrict__ be,
                  const float* __restrict__ Wf, const float* __restrict__ bf) {
    const int b = blockIdx.x >> 3;
    const int gr = blockIdx.x & 7;
    __shared__ float P[16][DIN];
    __shared__ float AE[16][DIN];
    const int tid = threadIdx.x;

    for (int i = tid; i < 16 * DIN; i += 256) {
        int r = i >> 8;
        int d = i & 255;
        P[r][d] = d_pooled[((b * N_) + gr * 16 + r) * DIN + d];
    }
    __syncthreads();

    const int o = tid;
    for (int r = 0; r < 16; r++) {
        float sa = ba[o], se = be[o];
#pragma unroll 4
        for (int d = 0; d < DIN; d++) {
            float p = P[r][d];
            sa += p * Wa[o * DIN + d];
            se += p * We[o * DIN + d];
        }
        float att = 1.0f / (1.0f + expf(-sa));
        float emb = tanhf(se);
        AE[r][o] = att * emb;
    }
    __syncthreads();

    const int o2 = tid & 63;
    const int rg = tid >> 6;
    for (int rp = 0; rp < 4; rp++) {
        int r = rp * 4 + rg;
        float sg = bf[o2];
#pragma unroll 4
        for (int d = 0; d < DIN; d++) sg += AE[r][d] * Wf[o2 * DIN + d];
        d_g[((b * N_) + gr * 16 + r) * DOUT + o2] = sg;
    }
}

// ---------------------------------------------------------------------------
// Kernel 5: out[b,o] = sum_n g[b,n,o] / N + max_n g[b,n,o]
// ---------------------------------------------------------------------------
__global__ void final_kernel(float* __restrict__ out) {
    const int b = blockIdx.x;
    const int o = threadIdx.x;
    float s = 0.f, m = -1e30f;
    for (int n = 0; n < N_; n++) {
        float v = d_g[((b * N_) + n) * DOUT + o];
        s += v;
        m = fmaxf(m, v);
    }
    out[b * DOUT + o] = s / (float)N_ + m;
}

// ---------------------------------------------------------------------------
extern "C" void kernel_launch(void* const* d_in, const int* in_sizes, int n_in,
                              void* d_out, int out_size) {
    const float* x      = (const float*)d_in[0];
    const int*   seqlen = (const int*)  d_in[1];
    const float* W1     = (const float*)d_in[2];
    const float* b1     = (const float*)d_in[3];
    const float* wlen   = (const float*)d_in[4];
    const float* Wa     = (const float*)d_in[5];
    const float* ba     = (const float*)d_in[6];
    const float* We     = (const float*)d_in[7];
    const float* be     = (const float*)d_in[8];
    const float* Wf     = (const float*)d_in[9];
    const float* bf     = (const float*)d_in[10];
    float* out = (float*)d_out;

    cudaFuncSetAttribute(scores_mma,
                         cudaFuncAttributeMaxDynamicSharedMemorySize, DYN_SMEM);
    scores_mma<<<GRID_SC, 512, DYN_SMEM>>>(x, W1, b1, wlen, seqlen);
    softmax_kernel<<<B_ * N_ / 8, 256>>>();
    pooled_kernel<<<B_ * N_, 512>>>(x);
    gated_kernel<<<B_ * 8, 256>>>(Wa, ba, We, be, Wf, bf);
    final_kernel<<<B_, 64>>>(out);
}

// round 9
// speedup vs baseline: 1.4295x; 1.0044x over previous
#include <cuda_runtime.h>
#include <cuda_fp16.h>
#include <math.h>
#include <cstdint>

#define B_    8
#define S_    512
#define N_    128
#define DIN   256
#define DOUT  64
#define DHID  128
#define M_TOT (B_*S_*N_)   // 524288 rows
#define NTILE (M_TOT/128)  // 4096 tiles
#define GRID_SC 148

// Scratch (no allocation allowed). d_scores layout: (b, n, s) transposed!
__device__ float d_scores[M_TOT];
__device__ float d_pooled[B_*N_*DIN];
__device__ float d_g[B_*N_*DOUT];

// ---------------------------------------------------------------------------
// Kernel 0: probe — shifts the fixed ncu capture window onto pooled_kernel.
// ---------------------------------------------------------------------------
__global__ void probe_kernel() {}

// ===========================================================================
// scores_mma: masked_score[b,n,s] = (relu(x @ W1^T + b1) . w_len) * mask(b,s)
// fp16 mma.sync m16n8k16, 2-term split on W. 512 threads.
// A path: 4-deep register-staged ring -> 8 outstanding LDG.128 per thread.
// ===========================================================================
#define KC      32
#define ASTRIDE 40
#define ASLAB   (128*ASTRIDE*2)
#define WSTRIDE 264
#define W_HI_OFF 0
#define W_LO_OFF (128*WSTRIDE*2)
#define A_OFF    (2*128*WSTRIDE*2)
#define DYN_SMEM (A_OFF + 2*ASLAB)

__device__ __forceinline__ uint32_t smem_u32(const void* p) {
    uint32_t a;
    asm("{ .reg .u64 t; cvta.to.shared.u64 t, %1; cvt.u32.u64 %0, t; }"
        : "=r"(a) : "l"(p));
    return a;
}
__device__ __forceinline__ void ldsm_x4(uint32_t addr, uint32_t* r) {
    asm volatile("ldmatrix.sync.aligned.m8n8.x4.shared.b16 {%0,%1,%2,%3}, [%4];"
                 : "=r"(r[0]), "=r"(r[1]), "=r"(r[2]), "=r"(r[3]) : "r"(addr));
}
__device__ __forceinline__ void mma_f16(float* c, const uint32_t* a,
                                        const uint32_t* b) {
    asm volatile(
        "mma.sync.aligned.m16n8k16.row.col.f32.f16.f16.f32 "
        "{%0,%1,%2,%3}, {%4,%5,%6,%7}, {%8,%9}, {%0,%1,%2,%3};"
        : "+f"(c[0]), "+f"(c[1]), "+f"(c[2]), "+f"(c[3])
        : "r"(a[0]), "r"(a[1]), "r"(a[2]), "r"(a[3]), "r"(b[0]), "r"(b[1]));
}
__device__ __forceinline__ uint32_t h2bits(__half2 h) {
    return *reinterpret_cast<uint32_t*>(&h);
}

__global__ __launch_bounds__(512)
void scores_mma(const float* __restrict__ x, const float* __restrict__ W1,
                const float* __restrict__ b1, const float* __restrict__ wlen,
                const int* __restrict__ seqlen) {
    extern __shared__ char dyn[];
    __shared__ float sb1[DHID], swl[DHID];
    __shared__ float red[128][4];

    const int tid = threadIdx.x;
    const int lane = tid & 31;
    const int wid = tid >> 5;
    const int warp_m = wid & 3;
    const int warp_n = wid >> 2;

    if (tid < DHID) { sb1[tid] = b1[tid]; swl[tid] = wlen[tid]; }

    // ---- W1 -> Whi/Wlo fp16 smem ----
    {
        __half* Whi = (__half*)(dyn + W_HI_OFF);
        __half* Wlo = (__half*)(dyn + W_LO_OFF);
#pragma unroll
        for (int it = 0; it < 16; it++) {
            int i = tid + it * 512;
            int n = i >> 6;
            int k4 = i & 63;
            float4 v = ((const float4*)W1)[i];
            __half hx = __float2half_rn(v.x), hy = __float2half_rn(v.y);
            __half hz = __float2half_rn(v.z), hw = __float2half_rn(v.w);
            float rx = v.x - __half2float(hx), ry = v.y - __half2float(hy);
            float rz = v.z - __half2float(hz), rw = v.w - __half2float(hw);
            int off = n * WSTRIDE + k4 * 4;
            uint2 hi, lo;
            hi.x = h2bits(__halves2half2(hx, hy));
            hi.y = h2bits(__halves2half2(hz, hw));
            lo.x = h2bits(__floats2half2_rn(rx, ry));
            lo.y = h2bits(__floats2half2_rn(rz, rw));
            *(uint2*)(Whi + off) = hi;
            *(uint2*)(Wlo + off) = lo;
        }
    }

    const uint32_t dbase = smem_u32(dyn);
    const uint32_t WhiU = dbase + W_HI_OFF, WloU = dbase + W_LO_OFF;
    const uint32_t AU = dbase + A_OFF;
    char* Abase = dyn + A_OFF;

    const int am = lane & 15;
    const int ak = (lane >> 4) * 8;
    const int bn = (lane & 7) + ((lane >> 4) << 3);
    const int bk8 = ((lane >> 3) & 1) * 8;

    const int arow = tid >> 3;
    const int acol = tid & 7;

    // 4-deep register staging ring: st[slot][p]
    float4 st[4][2];

#define LOAD_ST(slot, src) do {                                               \
        const float* _s = (src);                                              \
        st[slot][0] = *(const float4*)(_s + (long)arow * DIN + acol * 4);     \
        st[slot][1] = *(const float4*)(_s + (long)(arow + 64) * DIN + acol * 4); \
    } while (0)

#define CONV_STORE(slot, stage) do {                                          \
        char* _A = Abase + (stage) * ASLAB;                                   \
        _Pragma("unroll")                                                     \
        for (int p = 0; p < 2; p++) {                                         \
            int row = arow + p * 64;                                          \
            uint2 w;                                                          \
            w.x = h2bits(__floats2half2_rn(st[slot][p].x, st[slot][p].y));    \
            w.y = h2bits(__floats2half2_rn(st[slot][p].z, st[slot][p].w));    \
            *(uint2*)(_A + row * 80 + acol * 8) = w;                          \
        }                                                                     \
    } while (0)

    // prologue: chunks 0..3 of first tile
    {
        const float* Ag0 = x + (long)blockIdx.x * 128 * DIN;
#pragma unroll
        for (int c = 0; c < 4; c++) LOAD_ST(c, Ag0 + c * KC);
    }

    for (long tile = blockIdx.x; tile < NTILE; tile += GRID_SC) {
        float acc[2][4][4];
#pragma unroll
        for (int mt = 0; mt < 2; mt++)
#pragma unroll
            for (int j = 0; j < 4; j++)
#pragma unroll
                for (int e = 0; e < 4; e++) acc[mt][j][e] = 0.f;

        const float* Ag0 = x + tile * 128 * DIN;
        const float* Agn = x + (tile + GRID_SC) * 128 * DIN;
        const bool more = (tile + GRID_SC) < NTILE;

#pragma unroll
        for (int c = 0; c < 8; c++) {
            CONV_STORE(c & 3, c & 1);
            // refill slot with chunk c+4 (current tile c+4<8, else next tile)
            if (c < 4) LOAD_ST(c & 3, Ag0 + (c + 4) * KC);
            else if (more) LOAD_ST(c & 3, Agn + (c - 4) * KC);
            __syncthreads();

            const uint32_t Ast = AU + (uint32_t)(c & 1) * ASLAB;
#pragma unroll
            for (int ks = 0; ks < 2; ks++) {
                uint32_t ah[2][4];
#pragma unroll
                for (int mt = 0; mt < 2; mt++) {
                    uint32_t ao = Ast + (uint32_t)((warp_m * 32 + mt * 16 + am) * 80
                                                   + (ks * 16 + ak) * 2);
                    ldsm_x4(ao, ah[mt]);
                }
                uint32_t bh[2][4], bl[2][4];
                const int kk = c * KC + ks * 16;
#pragma unroll
                for (int q = 0; q < 2; q++) {
                    uint32_t bo = (uint32_t)((warp_n * 32 + q * 16 + bn) * WSTRIDE
                                             + kk + bk8) * 2;
                    ldsm_x4(WhiU + bo, bh[q]);
                    ldsm_x4(WloU + bo, bl[q]);
                }
#pragma unroll
                for (int mt = 0; mt < 2; mt++)
#pragma unroll
                    for (int q = 0; q < 2; q++) {
                        mma_f16(acc[mt][2 * q],     ah[mt], &bh[q][0]);
                        mma_f16(acc[mt][2 * q],     ah[mt], &bl[q][0]);
                        mma_f16(acc[mt][2 * q + 1], ah[mt], &bh[q][2]);
                        mma_f16(acc[mt][2 * q + 1], ah[mt], &bl[q][2]);
                    }
            }
            __syncthreads();
        }

        // --- epilogue: relu(+b1).wlen, reduce over n-groups ---
        float part[2][2] = {{0.f, 0.f}, {0.f, 0.f}};
#pragma unroll
        for (int j = 0; j < 4; j++) {
            int n0 = warp_n * 32 + j * 8 + (lane & 3) * 2;
            float bb0 = sb1[n0], bb1 = sb1[n0 + 1];
            float w0 = swl[n0], w1 = swl[n0 + 1];
#pragma unroll
            for (int mt = 0; mt < 2; mt++) {
                part[mt][0] += fmaxf(acc[mt][j][0] + bb0, 0.f) * w0
                             + fmaxf(acc[mt][j][1] + bb1, 0.f) * w1;
                part[mt][1] += fmaxf(acc[mt][j][2] + bb0, 0.f) * w0
                             + fmaxf(acc[mt][j][3] + bb1, 0.f) * w1;
            }
        }
#pragma unroll
        for (int d = 1; d <= 2; d <<= 1)
#pragma unroll
            for (int mt = 0; mt < 2; mt++) {
                part[mt][0] += __shfl_xor_sync(0xffffffffu, part[mt][0], d);
                part[mt][1] += __shfl_xor_sync(0xffffffffu, part[mt][1], d);
            }
        if ((lane & 3) == 0) {
            int g = lane >> 2;
#pragma unroll
            for (int mt = 0; mt < 2; mt++) {
                red[warp_m * 32 + mt * 16 + g][warp_n]     = part[mt][0];
                red[warp_m * 32 + mt * 16 + 8 + g][warp_n] = part[mt][1];
            }
        }
        __syncthreads();
        if (tid < 128) {
            const int b = (int)(tile / S_);
            const int s = (int)(tile % S_);
            float sc = red[tid][0] + red[tid][1] + red[tid][2] + red[tid][3];
            sc *= (s < seqlen[b]) ? 1.0f : -10.0f;
            d_scores[((long)b * N_ + tid) * S_ + s] = sc;
        }
        __syncthreads();
    }
#undef LOAD_ST
#undef CONV_STORE
}

// ---------------------------------------------------------------------------
// Kernel 2: softmax over contiguous s rows. Warp per (b,n) row, regs only.
// ---------------------------------------------------------------------------
__global__ __launch_bounds__(256)
void softmax_kernel() {
    const int row = blockIdx.x * 8 + (threadIdx.x >> 5);
    const int lane = threadIdx.x & 31;
    float* base = d_scores + (long)row * S_;

    float v[16];
    float lmax = -1e30f;
#pragma unroll
    for (int i = 0; i < 16; i++) {
        v[i] = base[lane + i * 32];
        lmax = fmaxf(lmax, v[i]);
    }
#pragma unroll
    for (int o = 16; o > 0; o >>= 1)
        lmax = fmaxf(lmax, __shfl_xor_sync(0xffffffffu, lmax, o));
    float lsum = 0.f;
#pragma unroll
    for (int i = 0; i < 16; i++) {
        v[i] = expf(v[i] - lmax);
        lsum += v[i];
    }
#pragma unroll
    for (int o = 16; o > 0; o >>= 1)
        lsum += __shfl_xor_sync(0xffffffffu, lsum, o);
    const float inv = 1.0f / lsum;
#pragma unroll
    for (int i = 0; i < 16; i++)
        base[lane + i * 32] = v[i] * inv;
}

// ---------------------------------------------------------------------------
// Kernel 3: pooled[b,n,d] = sum_s attn[b,n,s] * x[b,s,n,d]
// 512 threads: 8 s-groups x 64 float4-lanes, unroll 16 -> deep MLP.
// ---------------------------------------------------------------------------
__global__ __launch_bounds__(512)
void pooled_kernel(const float* __restrict__ x) {
    const int b = blockIdx.x >> 7;
    const int n = blockIdx.x & 127;
    __shared__ float a[S_];
    __shared__ float4 part[8][64];

    const int tid = threadIdx.x;
    a[tid] = d_scores[((long)(b * N_ + n)) * S_ + tid];
    __syncthreads();

    const int sg = tid >> 6;          // 0..7 : s eighth
    const int dq = tid & 63;          // float4 index over DIN
    const float4* xp = (const float4*)(x + ((long)(b * S_ + sg * 64) * N_ + n) * DIN)
                       + dq;
    const float* aq = a + sg * 64;
    const long stride4 = (long)N_ * DIN / 4;   // float4 stride per s

    float4 acc = make_float4(0.f, 0.f, 0.f, 0.f);
#pragma unroll 16
    for (int s = 0; s < 64; s++) {
        float w = aq[s];
        float4 v = xp[(long)s * stride4];
        acc.x += w * v.x; acc.y += w * v.y;
        acc.z += w * v.z; acc.w += w * v.w;
    }
    part[sg][dq] = acc;
    __syncthreads();
    if (tid < 64) {
        float4 r = part[0][tid];
#pragma unroll
        for (int g = 1; g < 8; g++) {
            float4 p = part[g][tid];
            r.x += p.x; r.y += p.y; r.z += p.z; r.w += p.w;
        }
        ((float4*)(d_pooled + ((long)(b * N_ + n)) * DIN))[tid] = r;
    }
}

// ---------------------------------------------------------------------------
// Kernel 4: gated readout
// ---------------------------------------------------------------------------
__global__ __launch_bounds__(256)
void gated_kernel(const float* __restrict__ Wa, const float* __restrict__ ba,
                  const float* __restrict__ We, const float* __restrict__ be,
                  const float* __restrict__ Wf, const float* __restrict__ bf) {
    const int b = blockIdx.x >> 3;
    const int gr = blockIdx.x & 7;
    __shared__ float P[16][DIN];
    __shared__ float AE[16][DIN];
    const int tid = threadIdx.x;

    for (int i = tid; i < 16 * DIN; i += 256) {
        int r = i >> 8;
        int d = i & 255;
        P[r][d] = d_pooled[((b * N_) + gr * 16 + r) * DIN + d];
    }
    __syncthreads();

    const int o = tid;
    for (int r = 0; r < 16; r++) {
        float sa = ba[o], se = be[o];
#pragma unroll 4
        for (int d = 0; d < DIN; d++) {
            float p = P[r][d];
            sa += p * Wa[o * DIN + d];
            se += p * We[o * DIN + d];
        }
        float att = 1.0f / (1.0f + expf(-sa));
        float emb = tanhf(se);
        AE[r][o] = att * emb;
    }
    __syncthreads();

    const int o2 = tid & 63;
    const int rg = tid >> 6;
    for (int rp = 0; rp < 4; rp++) {
        int r = rp * 4 + rg;
        float sg = bf[o2];
#pragma unroll 4
        for (int d = 0; d < DIN; d++) sg += AE[r][d] * Wf[o2 * DIN + d];
        d_g[((b * N_) + gr * 16 + r) * DOUT + o2] = sg;
    }
}

// ---------------------------------------------------------------------------
// Kernel 5: out[b,o] = sum_n g[b,n,o] / N + max_n g[b,n,o]
// ---------------------------------------------------------------------------
__global__ void final_kernel(float* __restrict__ out) {
    const int b = blockIdx.x;
    const int o = threadIdx.x;
    float s = 0.f, m = -1e30f;
    for (int n = 0; n < N_; n++) {
        float v = d_g[((b * N_) + n) * DOUT + o];
        s += v;
        m = fmaxf(m, v);
    }
    out[b * DOUT + o] = s / (float)N_ + m;
}

// ---------------------------------------------------------------------------
extern "C" void kernel_launch(void* const* d_in, const int* in_sizes, int n_in,
                              void* d_out, int out_size) {
    const float* x      = (const float*)d_in[0];
    const int*   seqlen = (const int*)  d_in[1];
    const float* W1     = (const float*)d_in[2];
    const float* b1     = (const float*)d_in[3];
    const float* wlen   = (const float*)d_in[4];
    const float* Wa     = (const float*)d_in[5];
    const float* ba     = (const float*)d_in[6];
    const float* We     = (const float*)d_in[7];
    const float* be     = (const float*)d_in[8];
    const float* Wf     = (const float*)d_in[9];
    const float* bf     = (const float*)d_in[10];
    float* out = (float*)d_out;

    cudaFuncSetAttribute(scores_mma,
                         cudaFuncAttributeMaxDynamicSharedMemorySize, DYN_SMEM);
    probe_kernel<<<1, 32>>>();
    scores_mma<<<GRID_SC, 512, DYN_SMEM>>>(x, W1, b1, wlen, seqlen);
    softmax_kernel<<<B_ * N_ / 8, 256>>>();
    pooled_kernel<<<B_ * N_, 512>>>(x);
    gated_kernel<<<B_ * 8, 256>>>(Wa, ba, We, be, Wf, bf);
    final_kernel<<<B_, 64>>>(out);
}

// round 10
// speedup vs baseline: 1.4787x; 1.0344x over previous
#include <cuda_runtime.h>
#include <cuda_fp16.h>
#include <math.h>
#include <cstdint>

#define B_    8
#define S_    512
#define N_    128
#define DIN   256
#define DOUT  64
#define DHID  128
#define M_TOT (B_*S_*N_)   // 524288 rows
#define NTILE (M_TOT/128)  // 4096 tiles
#define GRID_SC 148

// Scratch (no allocation allowed). d_scores layout: (b, n, s) transposed!
__device__ float d_scores[M_TOT];
__device__ float d_pooled[B_*N_*DIN];
__device__ float d_g[B_*N_*DOUT];

// ---------------------------------------------------------------------------
// Kernel 0: probe — 3 copies shift the 4th-launch ncu window onto scores_mma.
// ---------------------------------------------------------------------------
__global__ void probe_kernel() {}

// ===========================================================================
// scores_mma: masked_score[b,n,s] = (relu(x @ W1^T + b1) . w_len) * mask(b,s)
// fp16 mma.sync m16n8k16, 1-term (x_h * W_h), fp32 accum. 512 threads.
// ===========================================================================
#define KC      32
#define ASTRIDE 40
#define ASLAB   (128*ASTRIDE*2)
#define WSTRIDE 264
#define W_HI_OFF 0
#define A_OFF    (128*WSTRIDE*2)          // 67584
#define DYN_SMEM (A_OFF + 2*ASLAB)        // 88064

__device__ __forceinline__ uint32_t smem_u32(const void* p) {
    uint32_t a;
    asm("{ .reg .u64 t; cvta.to.shared.u64 t, %1; cvt.u32.u64 %0, t; }"
        : "=r"(a) : "l"(p));
    return a;
}
__device__ __forceinline__ void ldsm_x4(uint32_t addr, uint32_t* r) {
    asm volatile("ldmatrix.sync.aligned.m8n8.x4.shared.b16 {%0,%1,%2,%3}, [%4];"
                 : "=r"(r[0]), "=r"(r[1]), "=r"(r[2]), "=r"(r[3]) : "r"(addr));
}
__device__ __forceinline__ void mma_f16(float* c, const uint32_t* a,
                                        const uint32_t* b) {
    asm volatile(
        "mma.sync.aligned.m16n8k16.row.col.f32.f16.f16.f32 "
        "{%0,%1,%2,%3}, {%4,%5,%6,%7}, {%8,%9}, {%0,%1,%2,%3};"
        : "+f"(c[0]), "+f"(c[1]), "+f"(c[2]), "+f"(c[3])
        : "r"(a[0]), "r"(a[1]), "r"(a[2]), "r"(a[3]), "r"(b[0]), "r"(b[1]));
}
__device__ __forceinline__ uint32_t h2bits(__half2 h) {
    return *reinterpret_cast<uint32_t*>(&h);
}

__global__ __launch_bounds__(512)
void scores_mma(const float* __restrict__ x, const float* __restrict__ W1,
                const float* __restrict__ b1, const float* __restrict__ wlen,
                const int* __restrict__ seqlen) {
    extern __shared__ char dyn[];
    __shared__ float sb1[DHID], swl[DHID];
    __shared__ float red[128][4];

    const int tid = threadIdx.x;
    const int lane = tid & 31;
    const int wid = tid >> 5;
    const int warp_m = wid & 3;
    const int warp_n = wid >> 2;

    if (tid < DHID) { sb1[tid] = b1[tid]; swl[tid] = wlen[tid]; }

    // ---- W1 -> Whi fp16 smem (single term) ----
    {
        __half* Whi = (__half*)(dyn + W_HI_OFF);
#pragma unroll
        for (int it = 0; it < 16; it++) {
            int i = tid + it * 512;
            int n = i >> 6;
            int k4 = i & 63;
            float4 v = ((const float4*)W1)[i];
            uint2 hi;
            hi.x = h2bits(__floats2half2_rn(v.x, v.y));
            hi.y = h2bits(__floats2half2_rn(v.z, v.w));
            *(uint2*)(Whi + n * WSTRIDE + k4 * 4) = hi;
        }
    }

    const uint32_t dbase = smem_u32(dyn);
    const uint32_t WhiU = dbase + W_HI_OFF;
    const uint32_t AU = dbase + A_OFF;
    char* Abase = dyn + A_OFF;

    const int am = lane & 15;
    const int ak = (lane >> 4) * 8;
    const int bn = (lane & 7) + ((lane >> 4) << 3);
    const int bk8 = ((lane >> 3) & 1) * 8;

    const int arow = tid >> 3;
    const int acol = tid & 7;

    // 4-deep register staging ring
    float4 st[4][2];

#define LOAD_ST(slot, src) do {                                               \
        const float* _s = (src);                                              \
        st[slot][0] = *(const float4*)(_s + (long)arow * DIN + acol * 4);     \
        st[slot][1] = *(const float4*)(_s + (long)(arow + 64) * DIN + acol * 4); \
    } while (0)

#define CONV_STORE(slot, stage) do {                                          \
        char* _A = Abase + (stage) * ASLAB;                                   \
        _Pragma("unroll")                                                     \
        for (int p = 0; p < 2; p++) {                                         \
            int row = arow + p * 64;                                          \
            uint2 w;                                                          \
            w.x = h2bits(__floats2half2_rn(st[slot][p].x, st[slot][p].y));    \
            w.y = h2bits(__floats2half2_rn(st[slot][p].z, st[slot][p].w));    \
            *(uint2*)(_A + row * 80 + acol * 8) = w;                          \
        }                                                                     \
    } while (0)

    {
        const float* Ag0 = x + (long)blockIdx.x * 128 * DIN;
#pragma unroll
        for (int c = 0; c < 4; c++) LOAD_ST(c, Ag0 + c * KC);
    }

    for (long tile = blockIdx.x; tile < NTILE; tile += GRID_SC) {
        float acc[2][4][4];
#pragma unroll
        for (int mt = 0; mt < 2; mt++)
#pragma unroll
            for (int j = 0; j < 4; j++)
#pragma unroll
                for (int e = 0; e < 4; e++) acc[mt][j][e] = 0.f;

        const float* Ag0 = x + tile * 128 * DIN;
        const float* Agn = x + (tile + GRID_SC) * 128 * DIN;
        const bool more = (tile + GRID_SC) < NTILE;

#pragma unroll
        for (int c = 0; c < 8; c++) {
            CONV_STORE(c & 3, c & 1);
            if (c < 4) LOAD_ST(c & 3, Ag0 + (c + 4) * KC);
            else if (more) LOAD_ST(c & 3, Agn + (c - 4) * KC);
            __syncthreads();

            const uint32_t Ast = AU + (uint32_t)(c & 1) * ASLAB;
#pragma unroll
            for (int ks = 0; ks < 2; ks++) {
                uint32_t ah[2][4];
#pragma unroll
                for (int mt = 0; mt < 2; mt++) {
                    uint32_t ao = Ast + (uint32_t)((warp_m * 32 + mt * 16 + am) * 80
                                                   + (ks * 16 + ak) * 2);
                    ldsm_x4(ao, ah[mt]);
                }
                uint32_t bh[2][4];
                const int kk = c * KC + ks * 16;
#pragma unroll
                for (int q = 0; q < 2; q++) {
                    uint32_t bo = (uint32_t)((warp_n * 32 + q * 16 + bn) * WSTRIDE
                                             + kk + bk8) * 2;
                    ldsm_x4(WhiU + bo, bh[q]);
                }
#pragma unroll
                for (int mt = 0; mt < 2; mt++)
#pragma unroll
                    for (int q = 0; q < 2; q++) {
                        mma_f16(acc[mt][2 * q],     ah[mt], &bh[q][0]);
                        mma_f16(acc[mt][2 * q + 1], ah[mt], &bh[q][2]);
                    }
            }
            __syncthreads();
        }

        // --- epilogue: relu(+b1).wlen, reduce over n-groups ---
        float part[2][2] = {{0.f, 0.f}, {0.f, 0.f}};
#pragma unroll
        for (int j = 0; j < 4; j++) {
            int n0 = warp_n * 32 + j * 8 + (lane & 3) * 2;
            float bb0 = sb1[n0], bb1 = sb1[n0 + 1];
            float w0 = swl[n0], w1 = swl[n0 + 1];
#pragma unroll
            for (int mt = 0; mt < 2; mt++) {
                part[mt][0] += fmaxf(acc[mt][j][0] + bb0, 0.f) * w0
                             + fmaxf(acc[mt][j][1] + bb1, 0.f) * w1;
                part[mt][1] += fmaxf(acc[mt][j][2] + bb0, 0.f) * w0
                             + fmaxf(acc[mt][j][3] + bb1, 0.f) * w1;
            }
        }
#pragma unroll
        for (int d = 1; d <= 2; d <<= 1)
#pragma unroll
            for (int mt = 0; mt < 2; mt++) {
                part[mt][0] += __shfl_xor_sync(0xffffffffu, part[mt][0], d);
                part[mt][1] += __shfl_xor_sync(0xffffffffu, part[mt][1], d);
            }
        if ((lane & 3) == 0) {
            int g = lane >> 2;
#pragma unroll
            for (int mt = 0; mt < 2; mt++) {
                red[warp_m * 32 + mt * 16 + g][warp_n]     = part[mt][0];
                red[warp_m * 32 + mt * 16 + 8 + g][warp_n] = part[mt][1];
            }
        }
        __syncthreads();
        if (tid < 128) {
            const int b = (int)(tile / S_);
            const int s = (int)(tile % S_);
            float sc = red[tid][0] + red[tid][1] + red[tid][2] + red[tid][3];
            sc *= (s < seqlen[b]) ? 1.0f : -10.0f;
            d_scores[((long)b * N_ + tid) * S_ + s] = sc;
        }
        __syncthreads();
    }
#undef LOAD_ST
#undef CONV_STORE
}

// ---------------------------------------------------------------------------
// Kernel 2: softmax over contiguous s rows. Warp per (b,n) row, regs only.
// ---------------------------------------------------------------------------
__global__ __launch_bounds__(256)
void softmax_kernel() {
    const int row = blockIdx.x * 8 + (threadIdx.x >> 5);
    const int lane = threadIdx.x & 31;
    float* base = d_scores + (long)row * S_;

    float v[16];
    float lmax = -1e30f;
#pragma unroll
    for (int i = 0; i < 16; i++) {
        v[i] = base[lane + i * 32];
        lmax = fmaxf(lmax, v[i]);
    }
#pragma unroll
    for (int o = 16; o > 0; o >>= 1)
        lmax = fmaxf(lmax, __shfl_xor_sync(0xffffffffu, lmax, o));
    float lsum = 0.f;
#pragma unroll
    for (int i = 0; i < 16; i++) {
        v[i] = expf(v[i] - lmax);
        lsum += v[i];
    }
#pragma unroll
    for (int o = 16; o > 0; o >>= 1)
        lsum += __shfl_xor_sync(0xffffffffu, lsum, o);
    const float inv = 1.0f / lsum;
#pragma unroll
    for (int i = 0; i < 16; i++)
        base[lane + i * 32] = v[i] * inv;
}

// ---------------------------------------------------------------------------
// Kernel 3: pooled[b,n,d] = sum_s attn[b,n,s] * x[b,s,n,d]
// ---------------------------------------------------------------------------
__global__ __launch_bounds__(512)
void pooled_kernel(const float* __restrict__ x) {
    const int b = blockIdx.x >> 7;
    const int n = blockIdx.x & 127;
    __shared__ float a[S_];
    __shared__ float4 part[8][64];

    const int tid = threadIdx.x;
    a[tid] = d_scores[((long)(b * N_ + n)) * S_ + tid];
    __syncthreads();

    const int sg = tid >> 6;
    const int dq = tid & 63;
    const float4* xp = (const float4*)(x + ((long)(b * S_ + sg * 64) * N_ + n) * DIN)
                       + dq;
    const float* aq = a + sg * 64;
    const long stride4 = (long)N_ * DIN / 4;

    float4 acc = make_float4(0.f, 0.f, 0.f, 0.f);
#pragma unroll 16
    for (int s = 0; s < 64; s++) {
        float w = aq[s];
        float4 v = xp[(long)s * stride4];
        acc.x += w * v.x; acc.y += w * v.y;
        acc.z += w * v.z; acc.w += w * v.w;
    }
    part[sg][dq] = acc;
    __syncthreads();
    if (tid < 64) {
        float4 r = part[0][tid];
#pragma unroll
        for (int g = 1; g < 8; g++) {
            float4 p = part[g][tid];
            r.x += p.x; r.y += p.y; r.z += p.z; r.w += p.w;
        }
        ((float4*)(d_pooled + ((long)(b * N_ + n)) * DIN))[tid] = r;
    }
}

// ---------------------------------------------------------------------------
// Kernel 4: gated readout
// ---------------------------------------------------------------------------
__global__ __launch_bounds__(256)
void gated_kernel(const float* __restrict__ Wa, const float* __restrict__ ba,
                  const float* __restrict__ We, const float* __restrict__ be,
                  const float* __restrict__ Wf, const float* __restrict__ bf) {
    const int b = blockIdx.x >> 3;
    const int gr = blockIdx.x & 7;
    __shared__ float P[16][DIN];
    __shared__ float AE[16][DIN];
    const int tid = threadIdx.x;

    for (int i = tid; i < 16 * DIN; i += 256) {
        int r = i >> 8;
        int d = i & 255;
        P[r][d] = d_pooled[((b * N_) + gr * 16 + r) * DIN + d];
    }
    __syncthreads();

    const int o = tid;
    for (int r = 0; r < 16; r++) {
        float sa = ba[o], se = be[o];
#pragma unroll 4
        for (int d = 0; d < DIN; d++) {
            float p = P[r][d];
            sa += p * Wa[o * DIN + d];
            se += p * We[o * DIN + d];
        }
        float att = 1.0f / (1.0f + expf(-sa));
        float emb = tanhf(se);
        AE[r][o] = att * emb;
    }
    __syncthreads();

    const int o2 = tid & 63;
    const int rg = tid >> 6;
    for (int rp = 0; rp < 4; rp++) {
        int r = rp * 4 + rg;
        float sg = bf[o2];
#pragma unroll 4
        for (int d = 0; d < DIN; d++) sg += AE[r][d] * Wf[o2 * DIN + d];
        d_g[((b * N_) + gr * 16 + r) * DOUT + o2] = sg;
    }
}

// ---------------------------------------------------------------------------
// Kernel 5: out[b,o] = sum_n g[b,n,o] / N + max_n g[b,n,o]
// ---------------------------------------------------------------------------
__global__ void final_kernel(float* __restrict__ out) {
    const int b = blockIdx.x;
    const int o = threadIdx.x;
    float s = 0.f, m = -1e30f;
    for (int n = 0; n < N_; n++) {
        float v = d_g[((b * N_) + n) * DOUT + o];
        s += v;
        m = fmaxf(m, v);
    }
    out[b * DOUT + o] = s / (float)N_ + m;
}

// ---------------------------------------------------------------------------
extern "C" void kernel_launch(void* const* d_in, const int* in_sizes, int n_in,
                              void* d_out, int out_size) {
    const float* x      = (const float*)d_in[0];
    const int*   seqlen = (const int*)  d_in[1];
    const float* W1     = (const float*)d_in[2];
    const float* b1     = (const float*)d_in[3];
    const float* wlen   = (const float*)d_in[4];
    const float* Wa     = (const float*)d_in[5];
    const float* ba     = (const float*)d_in[6];
    const float* We     = (const float*)d_in[7];
    const float* be     = (const float*)d_in[8];
    const float* Wf     = (const float*)d_in[9];
    const float* bf     = (const float*)d_in[10];
    float* out = (float*)d_out;

    cudaFuncSetAttribute(scores_mma,
                         cudaFuncAttributeMaxDynamicSharedMemorySize, DYN_SMEM);
    probe_kernel<<<1, 32>>>();
    probe_kernel<<<1, 32>>>();
    probe_kernel<<<1, 32>>>();
    scores_mma<<<GRID_SC, 512, DYN_SMEM>>>(x, W1, b1, wlen, seqlen);
    softmax_kernel<<<B_ * N_ / 8, 256>>>();
    pooled_kernel<<<B_ * N_, 512>>>(x);
    gated_kernel<<<B_ * 8, 256>>>(Wa, ba, We, be, Wf, bf);
    final_kernel<<<B_, 64>>>(out);
}

// round 14
// speedup vs baseline: 1.4856x; 1.0047x over previous
#include <cuda_runtime.h>
#include <cuda_fp16.h>
#include <math.h>
#include <cstdint>

#define B_    8
#define S_    512
#define N_    128
#define DIN   256
#define DOUT  64
#define DHID  128
#define M_TOT (B_*S_*N_)   // 524288 rows
#define NTILE (M_TOT/128)  // 4096 tiles
#define GRID_SC 148

// Scratch (no allocation allowed). d_scores layout: (b, n, s), raw masked scores.
__device__ float d_scores[M_TOT];
__device__ float d_pooled[B_*N_*DIN];
__device__ float d_g[B_*N_*DOUT];

// ===========================================================================
// scores_mma: masked_score[b,n,s] = (relu(x @ W1^T + b1) . w_len) * mask(b,s)
// fp16 mma.sync m16n8k16, 1-term, fp32 accum. 512 threads, 1 sync/chunk.
// ===========================================================================
#define KC      32
#define ASTRIDE 40
#define ASLAB   (128*ASTRIDE*2)
#define WSTRIDE 264
#define W_HI_OFF 0
#define A_OFF    (128*WSTRIDE*2)          // 67584
#define DYN_SMEM (A_OFF + 2*ASLAB)        // 88064

__device__ __forceinline__ uint32_t smem_u32(const void* p) {
    uint32_t a;
    asm("{ .reg .u64 t; cvta.to.shared.u64 t, %1; cvt.u32.u64 %0, t; }"
        : "=r"(a) : "l"(p));
    return a;
}
__device__ __forceinline__ void ldsm_x4(uint32_t addr, uint32_t* r) {
    asm volatile("ldmatrix.sync.aligned.m8n8.x4.shared.b16 {%0,%1,%2,%3}, [%4];"
                 : "=r"(r[0]), "=r"(r[1]), "=r"(r[2]), "=r"(r[3]) : "r"(addr));
}
__device__ __forceinline__ void mma_f16(float* c, const uint32_t* a,
                                        const uint32_t* b) {
    asm volatile(
        "mma.sync.aligned.m16n8k16.row.col.f32.f16.f16.f32 "
        "{%0,%1,%2,%3}, {%4,%5,%6,%7}, {%8,%9}, {%0,%1,%2,%3};"
        : "+f"(c[0]), "+f"(c[1]), "+f"(c[2]), "+f"(c[3])
        : "r"(a[0]), "r"(a[1]), "r"(a[2]), "r"(a[3]), "r"(b[0]), "r"(b[1]));
}
__device__ __forceinline__ uint32_t h2bits(__half2 h) {
    return *reinterpret_cast<uint32_t*>(&h);
}

__global__ __launch_bounds__(512)
void scores_mma(const float* __restrict__ x, const float* __restrict__ W1,
                const float* __restrict__ b1, const float* __restrict__ wlen,
                const int* __restrict__ seqlen) {
    extern __shared__ char dyn[];
    __shared__ float sb1[DHID], swl[DHID];
    __shared__ float red[128][4];

    const int tid = threadIdx.x;
    const int lane = tid & 31;
    const int wid = tid >> 5;
    const int warp_m = wid & 3;
    const int warp_n = wid >> 2;

    if (tid < DHID) { sb1[tid] = b1[tid]; swl[tid] = wlen[tid]; }

    // ---- W1 -> Whi fp16 smem (single term) ----
    {
        __half* Whi = (__half*)(dyn + W_HI_OFF);
#pragma unroll
        for (int it = 0; it < 16; it++) {
            int i = tid + it * 512;
            int n = i >> 6;
            int k4 = i & 63;
            float4 v = ((const float4*)W1)[i];
            uint2 hi;
            hi.x = h2bits(__floats2half2_rn(v.x, v.y));
            hi.y = h2bits(__floats2half2_rn(v.z, v.w));
            *(uint2*)(Whi + n * WSTRIDE + k4 * 4) = hi;
        }
    }

    const uint32_t dbase = smem_u32(dyn);
    const uint32_t WhiU = dbase + W_HI_OFF;
    const uint32_t AU = dbase + A_OFF;
    char* Abase = dyn + A_OFF;

    const int am = lane & 15;
    const int ak = (lane >> 4) * 8;
    const int bn = (lane & 7) + ((lane >> 4) << 3);
    const int bk8 = ((lane >> 3) & 1) * 8;

    const int arow = tid >> 3;
    const int acol = tid & 7;

    float4 st[4][2];

#define LOAD_ST(slot, src) do {                                               \
        const float* _s = (src);                                              \
        st[slot][0] = *(const float4*)(_s + (long)arow * DIN + acol * 4);     \
        st[slot][1] = *(const float4*)(_s + (long)(arow + 64) * DIN + acol * 4); \
    } while (0)

#define CONV_STORE(slot, stage) do {                                          \
        char* _A = Abase + (stage) * ASLAB;                                   \
        _Pragma("unroll")                                                     \
        for (int p = 0; p < 2; p++) {                                         \
            int row = arow + p * 64;                                          \
            uint2 w;                                                          \
            w.x = h2bits(__floats2half2_rn(st[slot][p].x, st[slot][p].y));    \
            w.y = h2bits(__floats2half2_rn(st[slot][p].z, st[slot][p].w));    \
            *(uint2*)(_A + row * 80 + acol * 8) = w;                          \
        }                                                                     \
    } while (0)

    {
        const float* Ag0 = x + (long)blockIdx.x * 128 * DIN;
#pragma unroll
        for (int c = 0; c < 4; c++) LOAD_ST(c, Ag0 + c * KC);
    }

    for (long tile = blockIdx.x; tile < NTILE; tile += GRID_SC) {
        float acc[2][4][4];
#pragma unroll
        for (int mt = 0; mt < 2; mt++)
#pragma unroll
            for (int j = 0; j < 4; j++)
#pragma unroll
                for (int e = 0; e < 4; e++) acc[mt][j][e] = 0.f;

        const float* Ag0 = x + tile * 128 * DIN;
        const float* Agn = x + (tile + GRID_SC) * 128 * DIN;
        const bool more = (tile + GRID_SC) < NTILE;

#pragma unroll
        for (int c = 0; c < 8; c++) {
            CONV_STORE(c & 3, c & 1);
            if (c < 4) LOAD_ST(c & 3, Ag0 + (c + 4) * KC);
            else if (more) LOAD_ST(c & 3, Agn + (c - 4) * KC);
            __syncthreads();   // produce -> consume; also orders prior MMA reads
                               // of this stage (two iterations back) vs overwrite

            const uint32_t Ast = AU + (uint32_t)(c & 1) * ASLAB;
#pragma unroll
            for (int ks = 0; ks < 2; ks++) {
                uint32_t ah[2][4];
#pragma unroll
                for (int mt = 0; mt < 2; mt++) {
                    uint32_t ao = Ast + (uint32_t)((warp_m * 32 + mt * 16 + am) * 80
                                                   + (ks * 16 + ak) * 2);
                    ldsm_x4(ao, ah[mt]);
                }
                uint32_t bh[2][4];
                const int kk = c * KC + ks * 16;
#pragma unroll
                for (int q = 0; q < 2; q++) {
                    uint32_t bo = (uint32_t)((warp_n * 32 + q * 16 + bn) * WSTRIDE
                                             + kk + bk8) * 2;
                    ldsm_x4(WhiU + bo, bh[q]);
                }
#pragma unroll
                for (int mt = 0; mt < 2; mt++)
#pragma unroll
                    for (int q = 0; q < 2; q++) {
                        mma_f16(acc[mt][2 * q],     ah[mt], &bh[q][0]);
                        mma_f16(acc[mt][2 * q + 1], ah[mt], &bh[q][2]);
                    }
            }
            // no trailing sync: next iteration's sync provides the WAR barrier
        }

        // --- epilogue: relu(+b1).wlen, reduce over n-groups ---
        float part[2][2] = {{0.f, 0.f}, {0.f, 0.f}};
#pragma unroll
        for (int j = 0; j < 4; j++) {
            int n0 = warp_n * 32 + j * 8 + (lane & 3) * 2;
            float bb0 = sb1[n0], bb1 = sb1[n0 + 1];
            float w0 = swl[n0], w1 = swl[n0 + 1];
#pragma unroll
            for (int mt = 0; mt < 2; mt++) {
                part[mt][0] += fmaxf(acc[mt][j][0] + bb0, 0.f) * w0
                             + fmaxf(acc[mt][j][1] + bb1, 0.f) * w1;
                part[mt][1] += fmaxf(acc[mt][j][2] + bb0, 0.f) * w0
                             + fmaxf(acc[mt][j][3] + bb1, 0.f) * w1;
            }
        }
#pragma unroll
        for (int d = 1; d <= 2; d <<= 1)
#pragma unroll
            for (int mt = 0; mt < 2; mt++) {
                part[mt][0] += __shfl_xor_sync(0xffffffffu, part[mt][0], d);
                part[mt][1] += __shfl_xor_sync(0xffffffffu, part[mt][1], d);
            }
        __syncthreads();   // all MMA-stage reads done before red reuse below
        if ((lane & 3) == 0) {
            int g = lane >> 2;
#pragma unroll
            for (int mt = 0; mt < 2; mt++) {
                red[warp_m * 32 + mt * 16 + g][warp_n]     = part[mt][0];
                red[warp_m * 32 + mt * 16 + 8 + g][warp_n] = part[mt][1];
            }
        }
        __syncthreads();
        if (tid < 128) {
            const int b = (int)(tile / S_);
            const int s = (int)(tile % S_);
            float sc = red[tid][0] + red[tid][1] + red[tid][2] + red[tid][3];
            sc *= (s < seqlen[b]) ? 1.0f : -10.0f;
            d_scores[((long)b * N_ + tid) * S_ + s] = sc;
        }
        __syncthreads();
    }
#undef LOAD_ST
#undef CONV_STORE
}

// ---------------------------------------------------------------------------
// Kernel 2: fused softmax + pool. Block per (b,n), 512 threads.
//   attn = softmax_s(masked_scores[b,n,:]);  pooled[b,n,:] = sum_s attn*x[b,s,n,:]
// ---------------------------------------------------------------------------
__global__ __launch_bounds__(512)
void pool_kernel(const float* __restrict__ x) {
    const int b = blockIdx.x >> 7;
    const int n = blockIdx.x & 127;
    __shared__ float sv[S_];
    __shared__ float rbuf[16];
    __shared__ float4 part[8][64];

    const int tid = threadIdx.x;
    const int lane = tid & 31;
    const int wrp = tid >> 5;

    // softmax over the contiguous score row
    float v = d_scores[((long)(b * N_ + n)) * S_ + tid];
    float m = v;
#pragma unroll
    for (int o = 16; o > 0; o >>= 1)
        m = fmaxf(m, __shfl_xor_sync(0xffffffffu, m, o));
    if (lane == 0) rbuf[wrp] = m;
    __syncthreads();
    float bmax = rbuf[0];
#pragma unroll
    for (int w = 1; w < 16; w++) bmax = fmaxf(bmax, rbuf[w]);
    __syncthreads();

    float e = expf(v - bmax);
    float s = e;
#pragma unroll
    for (int o = 16; o > 0; o >>= 1)
        s += __shfl_xor_sync(0xffffffffu, s, o);
    if (lane == 0) rbuf[wrp] = s;
    __syncthreads();
    float bsum = 0.f;
#pragma unroll
    for (int w = 0; w < 16; w++) bsum += rbuf[w];
    sv[tid] = e * (1.0f / bsum);
    __syncthreads();

    // pooled: 8 s-groups x 64 float4-lanes
    const int sg = tid >> 6;
    const int dq = tid & 63;
    const float4* xp = (const float4*)(x + ((long)(b * S_ + sg * 64) * N_ + n) * DIN)
                       + dq;
    const float* aq = sv + sg * 64;
    const long stride4 = (long)N_ * DIN / 4;

    float4 acc = make_float4(0.f, 0.f, 0.f, 0.f);
#pragma unroll 16
    for (int si = 0; si < 64; si++) {
        float w = aq[si];
        float4 vv = xp[(long)si * stride4];
        acc.x += w * vv.x; acc.y += w * vv.y;
        acc.z += w * vv.z; acc.w += w * vv.w;
    }
    part[sg][dq] = acc;
    __syncthreads();
    if (tid < 64) {
        float4 r = part[0][tid];
#pragma unroll
        for (int g = 1; g < 8; g++) {
            float4 p = part[g][tid];
            r.x += p.x; r.y += p.y; r.z += p.z; r.w += p.w;
        }
        ((float4*)(d_pooled + ((long)(b * N_ + n)) * DIN))[tid] = r;
    }
}

// ---------------------------------------------------------------------------
// Kernel 3: gated readout
// ---------------------------------------------------------------------------
__global__ __launch_bounds__(256)
void gated_kernel(const float* __restrict__ Wa, const float* __restrict__ ba,
                  const float* __restrict__ We, const float* __restrict__ be,
                  const float* __restrict__ Wf, const float* __restrict__ bf) {
    const int b = blockIdx.x >> 3;
    const int gr = blockIdx.x & 7;
    __shared__ float P[16][DIN];
    __shared__ float AE[16][DIN];
    const int tid = threadIdx.x;

    for (int i = tid; i < 16 * DIN; i += 256) {
        int r = i >> 8;
        int d = i & 255;
        P[r][d] = d_pooled[((b * N_) + gr * 16 + r) * DIN + d];
    }
    __syncthreads();

    const int o = tid;
    for (int r = 0; r < 16; r++) {
        float sa = ba[o], se = be[o];
#pragma unroll 4
        for (int d = 0; d < DIN; d++) {
            float p = P[r][d];
            sa += p * Wa[o * DIN + d];
            se += p * We[o * DIN + d];
        }
        float att = 1.0f / (1.0f + expf(-sa));
        float emb = tanhf(se);
        AE[r][o] = att * emb;
    }
    __syncthreads();

    const int o2 = tid & 63;
    const int rg = tid >> 6;
    for (int rp = 0; rp < 4; rp++) {
        int r = rp * 4 + rg;
        float sg = bf[o2];
#pragma unroll 4
        for (int d = 0; d < DIN; d++) sg += AE[r][d] * Wf[o2 * DIN + d];
        d_g[((b * N_) + gr * 16 + r) * DOUT + o2] = sg;
    }
}

// ---------------------------------------------------------------------------
// Kernel 4: out[b,o] = sum_n g[b,n,o] / N + max_n g[b,n,o]
// 8 blocks x 256 threads: o = tid&63, 4 n-groups of 32, unrolled loads.
// ---------------------------------------------------------------------------
__global__ __launch_bounds__(256)
void final_kernel(float* __restrict__ out) {
    const int b = blockIdx.x;
    const int o = threadIdx.x & 63;
    const int g = threadIdx.x >> 6;    // 0..3
    __shared__ float ss[4][64], sm[4][64];

    const float* gp = d_g + ((long)(b * N_) + g * 32) * DOUT + o;
    float s = 0.f, m = -1e30f;
#pragma unroll
    for (int n = 0; n < 32; n++) {
        float v = gp[n * DOUT];
        s += v;
        m = fmaxf(m, v);
    }
    ss[g][o] = s;
    sm[g][o] = m;
    __syncthreads();
    if (threadIdx.x < 64) {
        int t = threadIdx.x;
        float S = (ss[0][t] + ss[1][t]) + (ss[2][t] + ss[3][t]);
        float M = fmaxf(fmaxf(sm[0][t], sm[1][t]), fmaxf(sm[2][t], sm[3][t]));
        out[b * DOUT + t] = S / (float)N_ + M;
    }
}

// ---------------------------------------------------------------------------
extern "C" void kernel_launch(void* const* d_in, const int* in_sizes, int n_in,
                              void* d_out, int out_size) {
    const float* x      = (const float*)d_in[0];
    const int*   seqlen = (const int*)  d_in[1];
    const float* W1     = (const float*)d_in[2];
    const float* b1     = (const float*)d_in[3];
    const float* wlen   = (const float*)d_in[4];
    const float* Wa     = (const float*)d_in[5];
    const float* ba     = (const float*)d_in[6];
    const float* We     = (const float*)d_in[7];
    const float* be     = (const float*)d_in[8];
    const float* Wf     = (const float*)d_in[9];
    const float* bf     = (const float*)d_in[10];
    float* out = (float*)d_out;

    cudaFuncSetAttribute(scores_mma,
                         cudaFuncAttributeMaxDynamicSharedMemorySize, DYN_SMEM);
    scores_mma<<<GRID_SC, 512, DYN_SMEM>>>(x, W1, b1, wlen, seqlen);
    pool_kernel<<<B_ * N_, 512>>>(x);
    gated_kernel<<<B_ * 8, 256>>>(Wa, ba, We, be, Wf, bf);
    final_kernel<<<B_, 256>>>(out);
}

// round 16
// speedup vs baseline: 1.4980x; 1.0083x over previous
#include <cuda_runtime.h>
#include <cuda_fp16.h>
#include <math.h>
#include <cstdint>

#define B_    8
#define S_    512
#define N_    128
#define DIN   256
#define DOUT  64
#define DHID  128
#define NBN   (B_*N_)      // 1024 (b,n) pairs
#define GRID_SC 148
#define RS    (N_*DIN)     // x row stride in floats (s -> s+1)

// Scratch (no allocation allowed)
__device__ float d_pooled[B_*N_*DIN];
__device__ float d_g[B_*N_*DOUT];

// ===========================================================================
// scorepool: per (b,n): scores = relu(x W1^T + b1).wlen * mask; online softmax
// over s; pooled = sum_s attn*x — x read ONCE (GEMV on smem-resident tile).
// fp16 mma m16n8k16 (hi term only, == R14 math); pooling uses hi+lo fp16.
// ===========================================================================
#define KC      32
#define WSTRIDE 264
#define CHUNKB  8192                       // 128 rows * 64 B (fp16, swizzled)
#define W_HI_OFF 0
#define A_HI_OFF (128*WSTRIDE*2)           // 67584
#define A_LO_OFF (A_HI_OFF + 8*CHUNKB)     // 133120
#define DYN_SMEM (A_LO_OFF + 8*CHUNKB)     // 198656

__device__ __forceinline__ uint32_t smem_u32(const void* p) {
    uint32_t a;
    asm("{ .reg .u64 t; cvta.to.shared.u64 t, %1; cvt.u32.u64 %0, t; }"
        : "=r"(a) : "l"(p));
    return a;
}
__device__ __forceinline__ void ldsm_x4(uint32_t addr, uint32_t* r) {
    asm volatile("ldmatrix.sync.aligned.m8n8.x4.shared.b16 {%0,%1,%2,%3}, [%4];"
                 : "=r"(r[0]), "=r"(r[1]), "=r"(r[2]), "=r"(r[3]) : "r"(addr));
}
__device__ __forceinline__ void mma_f16(float* c, const uint32_t* a,
                                        const uint32_t* b) {
    asm volatile(
        "mma.sync.aligned.m16n8k16.row.col.f32.f16.f16.f32 "
        "{%0,%1,%2,%3}, {%4,%5,%6,%7}, {%8,%9}, {%0,%1,%2,%3};"
        : "+f"(c[0]), "+f"(c[1]), "+f"(c[2]), "+f"(c[3])
        : "r"(a[0]), "r"(a[1]), "r"(a[2]), "r"(a[3]), "r"(b[0]), "r"(b[1]));
}
__device__ __forceinline__ uint32_t h2bits(__half2 h) {
    return *reinterpret_cast<uint32_t*>(&h);
}

__global__ __launch_bounds__(512)
void scorepool(const float* __restrict__ x, const float* __restrict__ W1,
               const float* __restrict__ b1, const float* __restrict__ wlen,
               const int* __restrict__ seqlen) {
    extern __shared__ char dyn[];
    __shared__ float sb1[DHID], swl[DHID];
    __shared__ float red[128][4];
    __shared__ float sw[128];
    __shared__ float accbuf[2][DIN];

    const int tid = threadIdx.x;
    const int lane = tid & 31;
    const int wid = tid >> 5;
    const int warp_m = wid & 3;
    const int warp_n = wid >> 2;

    if (tid < DHID) { sb1[tid] = b1[tid]; swl[tid] = wlen[tid]; }

    // ---- W1 -> Whi fp16 smem (GEMM term) ----
    {
        __half* Whi = (__half*)(dyn + W_HI_OFF);
#pragma unroll
        for (int it = 0; it < 16; it++) {
            int i = tid + it * 512;
            int n = i >> 6;
            int k4 = i & 63;
            float4 v = ((const float4*)W1)[i];
            uint2 hi;
            hi.x = h2bits(__floats2half2_rn(v.x, v.y));
            hi.y = h2bits(__floats2half2_rn(v.z, v.w));
            *(uint2*)(Whi + n * WSTRIDE + k4 * 4) = hi;
        }
    }

    const uint32_t dbase = smem_u32(dyn);
    const uint32_t WhiU = dbase + W_HI_OFF;
    const uint32_t AhiU = dbase + A_HI_OFF;

    const int am = lane & 15;            // ldmatrix row within 16
    const int akh = lane >> 4;           // k-half (0/1)
    const int bn_r = (lane & 7) + ((lane >> 4) << 3);
    const int bk8 = ((lane >> 3) & 1) * 8;

    const int arow = tid >> 3;           // load rows arow, arow+64
    const int acol = tid & 7;            // float4 within 32-float chunk row

    float4 st[4][2];

#define LOAD_ST(slot, src) do {                                               \
        const float* _s = (src);                                              \
        st[slot][0] = *(const float4*)(_s + (long)arow * RS + acol * 4);      \
        st[slot][1] = *(const float4*)(_s + (long)(arow + 64) * RS + acol * 4); \
    } while (0)

#define CONV_STORE(slot, creg) do {                                           \
        char* _Ah = dyn + A_HI_OFF + (creg) * CHUNKB;                         \
        char* _Al = dyn + A_LO_OFF + (creg) * CHUNKB;                         \
        _Pragma("unroll")                                                     \
        for (int p = 0; p < 2; p++) {                                         \
            int row = arow + p * 64;                                          \
            float4 v = st[slot][p];                                           \
            __half hx = __float2half_rn(v.x), hy = __float2half_rn(v.y);      \
            __half hz = __float2half_rn(v.z), hw = __float2half_rn(v.w);      \
            uint2 whi, wlo2;                                                  \
            whi.x = h2bits(__halves2half2(hx, hy));                           \
            whi.y = h2bits(__halves2half2(hz, hw));                           \
            wlo2.x = h2bits(__floats2half2_rn(v.x - __half2float(hx),         \
                                              v.y - __half2float(hy)));       \
            wlo2.y = h2bits(__floats2half2_rn(v.z - __half2float(hz),         \
                                              v.w - __half2float(hw)));       \
            uint32_t off = (uint32_t)(row * 64                                \
                         + ((((acol >> 1) ^ ((row >> 1) & 3))) << 4)          \
                         + ((acol & 1) << 3));                                \
            *(uint2*)(_Ah + off) = whi;                                       \
            *(uint2*)(_Al + off) = wlo2;                                      \
        }                                                                     \
    } while (0)

    // x tile base for (bn, t): rows are s = t*128 + row, n fixed
    auto tile_base = [&](int bn, int t) -> const float* {
        return x + (((long)(bn >> 7) * S_ + t * 128) * N_ + (bn & 127)) * DIN;
    };

    // prologue: chunks 0..3 of first tile
    {
        const float* cur0 = tile_base(blockIdx.x, 0);
#pragma unroll
        for (int c = 0; c < 4; c++) LOAD_ST(c, cur0 + c * KC);
    }
    __syncthreads();   // W ready

    const int d_col = tid & 255;         // GEMV column
    const int gv = tid >> 8;             // GEMV row group (0/1)
    const int gv_chunk = d_col >> 5;
    const int gv_unit = (d_col & 31) >> 3;
    const int gv_within = ((d_col & 31) & 7) * 2;

    for (int bn = blockIdx.x; bn < NBN; bn += GRID_SC) {
        const int len = seqlen[bn >> 7];
        float m_run = -1e30f, Z_run = 0.f, accp = 0.f;

#pragma unroll 1
        for (int t = 0; t < 4; t++) {
            const float* nxt = (t < 3) ? tile_base(bn, t + 1)
                             : ((bn + GRID_SC < NBN) ? tile_base(bn + GRID_SC, 0)
                                                     : (const float*)0);
            const float* cur = tile_base(bn, t);

            float acc[2][4][4];
#pragma unroll
            for (int mt = 0; mt < 2; mt++)
#pragma unroll
                for (int j = 0; j < 4; j++)
#pragma unroll
                    for (int e = 0; e < 4; e++) acc[mt][j][e] = 0.f;

#pragma unroll
            for (int c = 0; c < 8; c++) {
                CONV_STORE(c & 3, c);
                if (c < 4) LOAD_ST(c & 3, cur + (c + 4) * KC);
                else if (nxt) LOAD_ST(c & 3, nxt + (c - 4) * KC);
                __syncthreads();

#pragma unroll
                for (int ks = 0; ks < 2; ks++) {
                    uint32_t ah[2][4];
#pragma unroll
                    for (int mt = 0; mt < 2; mt++) {
                        int row = warp_m * 32 + mt * 16 + am;
                        int phys = (ks * 2 + akh) ^ ((row >> 1) & 3);
                        ldsm_x4(AhiU + c * CHUNKB + row * 64 + phys * 16, ah[mt]);
                    }
                    uint32_t bh[2][4];
                    const int kk = c * KC + ks * 16;
#pragma unroll
                    for (int q = 0; q < 2; q++) {
                        uint32_t bo = (uint32_t)((warp_n * 32 + q * 16 + bn_r)
                                                 * WSTRIDE + kk + bk8) * 2;
                        ldsm_x4(WhiU + bo, bh[q]);
                    }
#pragma unroll
                    for (int mt = 0; mt < 2; mt++)
#pragma unroll
                        for (int q = 0; q < 2; q++) {
                            mma_f16(acc[mt][2 * q],     ah[mt], &bh[q][0]);
                            mma_f16(acc[mt][2 * q + 1], ah[mt], &bh[q][2]);
                        }
                }
                // next iteration's sync is the WAR barrier (regions distinct)
            }

            // --- epilogue: relu(+b1).wlen, reduce -> raw masked scores sw ---
            float part[2][2] = {{0.f, 0.f}, {0.f, 0.f}};
#pragma unroll
            for (int j = 0; j < 4; j++) {
                int n0 = warp_n * 32 + j * 8 + (lane & 3) * 2;
                float bb0 = sb1[n0], bb1 = sb1[n0 + 1];
                float w0 = swl[n0], w1 = swl[n0 + 1];
#pragma unroll
                for (int mt = 0; mt < 2; mt++) {
                    part[mt][0] += fmaxf(acc[mt][j][0] + bb0, 0.f) * w0
                                 + fmaxf(acc[mt][j][1] + bb1, 0.f) * w1;
                    part[mt][1] += fmaxf(acc[mt][j][2] + bb0, 0.f) * w0
                                 + fmaxf(acc[mt][j][3] + bb1, 0.f) * w1;
                }
            }
#pragma unroll
            for (int d = 1; d <= 2; d <<= 1)
#pragma unroll
                for (int mt = 0; mt < 2; mt++) {
                    part[mt][0] += __shfl_xor_sync(0xffffffffu, part[mt][0], d);
                    part[mt][1] += __shfl_xor_sync(0xffffffffu, part[mt][1], d);
                }
            __syncthreads();
            if ((lane & 3) == 0) {
                int g = lane >> 2;
#pragma unroll
                for (int mt = 0; mt < 2; mt++) {
                    red[warp_m * 32 + mt * 16 + g][warp_n]     = part[mt][0];
                    red[warp_m * 32 + mt * 16 + 8 + g][warp_n] = part[mt][1];
                }
            }
            __syncthreads();
            if (tid < 128) {
                int s = t * 128 + tid;
                float sc = red[tid][0] + red[tid][1] + red[tid][2] + red[tid][3];
                sc *= (s < len) ? 1.0f : -10.0f;
                sw[tid] = sc;
            }
            __syncthreads();

            // --- online softmax update (warp-redundant reductions) ---
            float tmax;
            {
                float a0 = fmaxf(sw[lane], sw[lane + 32]);
                float a1 = fmaxf(sw[lane + 64], sw[lane + 96]);
                tmax = fmaxf(a0, a1);
#pragma unroll
                for (int o = 16; o > 0; o >>= 1)
                    tmax = fmaxf(tmax, __shfl_xor_sync(0xffffffffu, tmax, o));
            }
            float m_new = fmaxf(m_run, tmax);
            float f = expf(m_run - m_new);
            m_run = m_new;
            accp *= f;
            Z_run *= f;
            __syncthreads();              // everyone done reading raw sw
            if (tid < 128) sw[tid] = expf(sw[tid] - m_new);
            __syncthreads();
            {
                float z = (sw[lane] + sw[lane + 32])
                        + (sw[lane + 64] + sw[lane + 96]);
#pragma unroll
                for (int o = 16; o > 0; o >>= 1)
                    z += __shfl_xor_sync(0xffffffffu, z, o);
                Z_run += z;
            }

            // --- pooled GEMV on smem-resident tile (hi+lo = ~fp32 exact) ---
            {
                const char* Ah = dyn + A_HI_OFF + gv_chunk * CHUNKB;
                const char* Al = dyn + A_LO_OFF + gv_chunk * CHUNKB;
#pragma unroll 8
                for (int r = 0; r < 64; r++) {
                    int row = gv * 64 + r;
                    uint32_t off = (uint32_t)(row * 64
                                 + ((gv_unit ^ ((row >> 1) & 3)) << 4)
                                 + gv_within);
                    float xv = __half2float(*(const __half*)(Ah + off))
                             + __half2float(*(const __half*)(Al + off));
                    accp += sw[row] * xv;
                }
            }
            __syncthreads();              // protect A regions + sw for next tile
        }

        // --- write pooled[bn, :] ---
        accbuf[gv][d_col] = accp;
        __syncthreads();
        if (tid < DIN)
            d_pooled[(long)bn * DIN + tid] =
                (accbuf[0][tid] + accbuf[1][tid]) / Z_run;
        __syncthreads();
    }
#undef LOAD_ST
#undef CONV_STORE
}

// ---------------------------------------------------------------------------
// Kernel 2: gated readout
// ---------------------------------------------------------------------------
__global__ __launch_bounds__(256)
void gated_kernel(const float* __restrict__ Wa, const float* __restrict__ ba,
                  const float* __restrict__ We, const float* __restrict__ be,
                  const float* __restrict__ Wf, const float* __restrict__ bf) {
    const int b = blockIdx.x >> 3;
    const int gr = blockIdx.x & 7;
    __shared__ float P[16][DIN];
    __shared__ float AE[16][DIN];
    const int tid = threadIdx.x;

    for (int i = tid; i < 16 * DIN; i += 256) {
        int r = i >> 8;
        int d = i & 255;
        P[r][d] = d_pooled[((b * N_) + gr * 16 + r) * DIN + d];
    }
    __syncthreads();

    const int o = tid;
    for (int r = 0; r < 16; r++) {
        float sa = ba[o], se = be[o];
#pragma unroll 4
        for (int d = 0; d < DIN; d++) {
            float p = P[r][d];
            sa += p * Wa[o * DIN + d];
            se += p * We[o * DIN + d];
        }
        float att = 1.0f / (1.0f + expf(-sa));
        float emb = tanhf(se);
        AE[r][o] = att * emb;
    }
    __syncthreads();

    const int o2 = tid & 63;
    const int rg = tid >> 6;
    for (int rp = 0; rp < 4; rp++) {
        int r = rp * 4 + rg;
        float sg = bf[o2];
#pragma unroll 4
        for (int d = 0; d < DIN; d++) sg += AE[r][d] * Wf[o2 * DIN + d];
        d_g[((b * N_) + gr * 16 + r) * DOUT + o2] = sg;
    }
}

// ---------------------------------------------------------------------------
// Kernel 3: out[b,o] = sum_n g[b,n,o] / N + max_n g[b,n,o]
// ---------------------------------------------------------------------------
__global__ __launch_bounds__(256)
void final_kernel(float* __restrict__ out) {
    const int b = blockIdx.x;
    const int o = threadIdx.x & 63;
    const int g = threadIdx.x >> 6;
    __shared__ float ss[4][64], sm[4][64];

    const float* gp = d_g + ((long)(b * N_) + g * 32) * DOUT + o;
    float s = 0.f, m = -1e30f;
#pragma unroll
    for (int n = 0; n < 32; n++) {
        float v = gp[n * DOUT];
        s += v;
        m = fmaxf(m, v);
    }
    ss[g][o] = s;
    sm[g][o] = m;
    __syncthreads();
    if (threadIdx.x < 64) {
        int t = threadIdx.x;
        float S = (ss[0][t] + ss[1][t]) + (ss[2][t] + ss[3][t]);
        float M = fmaxf(fmaxf(sm[0][t], sm[1][t]), fmaxf(sm[2][t], sm[3][t]));
        out[b * DOUT + t] = S / (float)N_ + M;
    }
}

// ---------------------------------------------------------------------------
extern "C" void kernel_launch(void* const* d_in, const int* in_sizes, int n_in,
                              void* d_out, int out_size) {
    const float* x      = (const float*)d_in[0];
    const int*   seqlen = (const int*)  d_in[1];
    const float* W1     = (const float*)d_in[2];
    const float* b1     = (const float*)d_in[3];
    const float* wlen   = (const float*)d_in[4];
    const float* Wa     = (const float*)d_in[5];
    const float* ba     = (const float*)d_in[6];
    const float* We     = (const float*)d_in[7];
    const float* be     = (const float*)d_in[8];
    const float* Wf     = (const float*)d_in[9];
    const float* bf     = (const float*)d_in[10];
    float* out = (float*)d_out;

    cudaFuncSetAttribute(scorepool,
                         cudaFuncAttributeMaxDynamicSharedMemorySize, DYN_SMEM);
    scorepool<<<GRID_SC, 512, DYN_SMEM>>>(x, W1, b1, wlen, seqlen);
    gated_kernel<<<B_ * 8, 256>>>(Wa, ba, We, be, Wf, bf);
    final_kernel<<<B_, 256>>>(out);
}

// round 17
// speedup vs baseline: 1.5000x; 1.0014x over previous
#include <cuda_runtime.h>
#include <cuda_fp16.h>
#include <math.h>
#include <cstdint>

#define B_    8
#define S_    512
#define N_    128
#define DIN   256
#define DOUT  64
#define DHID  128
#define NBN   (B_*N_)      // 1024 (b,n) pairs
#define GRID_SC 148
#define RS    (N_*DIN)     // x row stride in floats (s -> s+1)

// Scratch (no allocation allowed)
__device__ float d_pooled[B_*N_*DIN];
__device__ float d_g[B_*N_*DOUT];

// ===========================================================================
// scorepool: per (b,n): scores = relu(x W1^T + b1).wlen * mask; online softmax
// over s; pooled = sum_s attn*x — x read ONCE (GEMV on smem-resident tile).
// fp16 mma m16n8k16 (hi term); pooling uses hi+lo fp16 (~fp32 exact), half2.
// ===========================================================================
#define KC      32
#define WSTRIDE 264
#define CHUNKB  8192                       // 128 rows * 64 B (fp16, swizzled)
#define W_HI_OFF 0
#define A_HI_OFF (128*WSTRIDE*2)           // 67584
#define A_LO_OFF (A_HI_OFF + 8*CHUNKB)     // 133120
#define DYN_SMEM (A_LO_OFF + 8*CHUNKB)     // 198656

__device__ __forceinline__ uint32_t smem_u32(const void* p) {
    uint32_t a;
    asm("{ .reg .u64 t; cvta.to.shared.u64 t, %1; cvt.u32.u64 %0, t; }"
        : "=r"(a) : "l"(p));
    return a;
}
__device__ __forceinline__ void ldsm_x4(uint32_t addr, uint32_t* r) {
    asm volatile("ldmatrix.sync.aligned.m8n8.x4.shared.b16 {%0,%1,%2,%3}, [%4];"
                 : "=r"(r[0]), "=r"(r[1]), "=r"(r[2]), "=r"(r[3]) : "r"(addr));
}
__device__ __forceinline__ void mma_f16(float* c, const uint32_t* a,
                                        const uint32_t* b) {
    asm volatile(
        "mma.sync.aligned.m16n8k16.row.col.f32.f16.f16.f32 "
        "{%0,%1,%2,%3}, {%4,%5,%6,%7}, {%8,%9}, {%0,%1,%2,%3};"
        : "+f"(c[0]), "+f"(c[1]), "+f"(c[2]), "+f"(c[3])
        : "r"(a[0]), "r"(a[1]), "r"(a[2]), "r"(a[3]), "r"(b[0]), "r"(b[1]));
}
__device__ __forceinline__ uint32_t h2bits(__half2 h) {
    return *reinterpret_cast<uint32_t*>(&h);
}

__global__ __launch_bounds__(512)
void scorepool(const float* __restrict__ x, const float* __restrict__ W1,
               const float* __restrict__ b1, const float* __restrict__ wlen,
               const int* __restrict__ seqlen) {
    extern __shared__ char dyn[];
    __shared__ float sb1[DHID], swl[DHID];
    __shared__ float red[128][4];
    __shared__ float sw[128];          // raw masked scores
    __shared__ float sw2[128];         // exp(scores - m)
    __shared__ float2 accbuf[4][128];

    const int tid = threadIdx.x;
    const int lane = tid & 31;
    const int wid = tid >> 5;
    const int warp_m = wid & 3;
    const int warp_n = wid >> 2;

    if (tid < DHID) { sb1[tid] = b1[tid]; swl[tid] = wlen[tid]; }

    // ---- W1 -> Whi fp16 smem (GEMM term) ----
    {
        __half* Whi = (__half*)(dyn + W_HI_OFF);
#pragma unroll
        for (int it = 0; it < 16; it++) {
            int i = tid + it * 512;
            int n = i >> 6;
            int k4 = i & 63;
            float4 v = ((const float4*)W1)[i];
            uint2 hi;
            hi.x = h2bits(__floats2half2_rn(v.x, v.y));
            hi.y = h2bits(__floats2half2_rn(v.z, v.w));
            *(uint2*)(Whi + n * WSTRIDE + k4 * 4) = hi;
        }
    }

    const uint32_t dbase = smem_u32(dyn);
    const uint32_t WhiU = dbase + W_HI_OFF;
    const uint32_t AhiU = dbase + A_HI_OFF;

    const int am = lane & 15;            // ldmatrix row within 16
    const int akh = lane >> 4;           // k-half (0/1)
    const int bn_r = (lane & 7) + ((lane >> 4) << 3);
    const int bk8 = ((lane >> 3) & 1) * 8;

    const int arow = tid >> 3;           // load rows arow, arow+64
    const int acol = tid & 7;            // float4 within 32-float chunk row

    float4 st[4][2];

#define LOAD_ST(slot, src) do {                                               \
        const float* _s = (src);                                              \
        st[slot][0] = *(const float4*)(_s + (long)arow * RS + acol * 4);      \
        st[slot][1] = *(const float4*)(_s + (long)(arow + 64) * RS + acol * 4); \
    } while (0)

#define CONV_STORE(slot, creg) do {                                           \
        char* _Ah = dyn + A_HI_OFF + (creg) * CHUNKB;                         \
        char* _Al = dyn + A_LO_OFF + (creg) * CHUNKB;                         \
        _Pragma("unroll")                                                     \
        for (int p = 0; p < 2; p++) {                                         \
            int row = arow + p * 64;                                          \
            float4 v = st[slot][p];                                           \
            __half hx = __float2half_rn(v.x), hy = __float2half_rn(v.y);      \
            __half hz = __float2half_rn(v.z), hw = __float2half_rn(v.w);      \
            uint2 whi, wlo2;                                                  \
            whi.x = h2bits(__halves2half2(hx, hy));                           \
            whi.y = h2bits(__halves2half2(hz, hw));                           \
            wlo2.x = h2bits(__floats2half2_rn(v.x - __half2float(hx),         \
                                              v.y - __half2float(hy)));       \
            wlo2.y = h2bits(__floats2half2_rn(v.z - __half2float(hz),         \
                                              v.w - __half2float(hw)));       \
            uint32_t off = (uint32_t)(row * 64                                \
                         + ((((acol >> 1) ^ ((row >> 1) & 3))) << 4)          \
                         + ((acol & 1) << 3));                                \
            *(uint2*)(_Ah + off) = whi;                                       \
            *(uint2*)(_Al + off) = wlo2;                                      \
        }                                                                     \
    } while (0)

    // x tile base for (bn, t): rows are s = t*128 + row, n fixed
    auto tile_base = [&](int bn, int t) -> const float* {
        return x + (((long)(bn >> 7) * S_ + t * 128) * N_ + (bn & 127)) * DIN;
    };

    // prologue: chunks 0..3 of first tile
    {
        const float* cur0 = tile_base(blockIdx.x, 0);
#pragma unroll
        for (int c = 0; c < 4; c++) LOAD_ST(c, cur0 + c * KC);
    }
    __syncthreads();   // W ready

    // GEMV mapping: 4 row-groups x 128 half2 column-pairs
    const int gvp = tid & 127;           // column pair (cols 2*gvp, 2*gvp+1)
    const int gvg = tid >> 7;            // row group (0..3), rows gvg*32..+31
    const int gv_chunk = gvp >> 4;       // 32 cols per chunk = 16 pairs
    const int gv_unit = (gvp & 15) >> 2;
    const int gv_within = ((gvp & 15) & 3) * 4;

    for (int bn = blockIdx.x; bn < NBN; bn += GRID_SC) {
        const int len = seqlen[bn >> 7];
        float m_run = -1e30f, Z_run = 0.f;
        float2 accp = make_float2(0.f, 0.f);

#pragma unroll 1
        for (int t = 0; t < 4; t++) {
            const float* nxt = (t < 3) ? tile_base(bn, t + 1)
                             : ((bn + GRID_SC < NBN) ? tile_base(bn + GRID_SC, 0)
                                                     : (const float*)0);
            const float* cur = tile_base(bn, t);

            float acc[2][4][4];
#pragma unroll
            for (int mt = 0; mt < 2; mt++)
#pragma unroll
                for (int j = 0; j < 4; j++)
#pragma unroll
                    for (int e = 0; e < 4; e++) acc[mt][j][e] = 0.f;

#pragma unroll
            for (int c = 0; c < 8; c++) {
                CONV_STORE(c & 3, c);
                if (c < 4) LOAD_ST(c & 3, cur + (c + 4) * KC);
                else if (nxt) LOAD_ST(c & 3, nxt + (c - 4) * KC);
                __syncthreads();

#pragma unroll
                for (int ks = 0; ks < 2; ks++) {
                    uint32_t ah[2][4];
#pragma unroll
                    for (int mt = 0; mt < 2; mt++) {
                        int row = warp_m * 32 + mt * 16 + am;
                        int phys = (ks * 2 + akh) ^ ((row >> 1) & 3);
                        ldsm_x4(AhiU + c * CHUNKB + row * 64 + phys * 16, ah[mt]);
                    }
                    uint32_t bh[2][4];
                    const int kk = c * KC + ks * 16;
#pragma unroll
                    for (int q = 0; q < 2; q++) {
                        uint32_t bo = (uint32_t)((warp_n * 32 + q * 16 + bn_r)
                                                 * WSTRIDE + kk + bk8) * 2;
                        ldsm_x4(WhiU + bo, bh[q]);
                    }
#pragma unroll
                    for (int mt = 0; mt < 2; mt++)
#pragma unroll
                        for (int q = 0; q < 2; q++) {
                            mma_f16(acc[mt][2 * q],     ah[mt], &bh[q][0]);
                            mma_f16(acc[mt][2 * q + 1], ah[mt], &bh[q][2]);
                        }
                }
                // next iteration's sync is the WAR barrier (regions distinct)
            }

            // --- epilogue: relu(+b1).wlen, reduce -> raw masked scores sw ---
            float part[2][2] = {{0.f, 0.f}, {0.f, 0.f}};
#pragma unroll
            for (int j = 0; j < 4; j++) {
                int n0 = warp_n * 32 + j * 8 + (lane & 3) * 2;
                float bb0 = sb1[n0], bb1 = sb1[n0 + 1];
                float w0 = swl[n0], w1 = swl[n0 + 1];
#pragma unroll
                for (int mt = 0; mt < 2; mt++) {
                    part[mt][0] += fmaxf(acc[mt][j][0] + bb0, 0.f) * w0
                                 + fmaxf(acc[mt][j][1] + bb1, 0.f) * w1;
                    part[mt][1] += fmaxf(acc[mt][j][2] + bb0, 0.f) * w0
                                 + fmaxf(acc[mt][j][3] + bb1, 0.f) * w1;
                }
            }
#pragma unroll
            for (int d = 1; d <= 2; d <<= 1)
#pragma unroll
                for (int mt = 0; mt < 2; mt++) {
                    part[mt][0] += __shfl_xor_sync(0xffffffffu, part[mt][0], d);
                    part[mt][1] += __shfl_xor_sync(0xffffffffu, part[mt][1], d);
                }
            if ((lane & 3) == 0) {
                int g = lane >> 2;
#pragma unroll
                for (int mt = 0; mt < 2; mt++) {
                    red[warp_m * 32 + mt * 16 + g][warp_n]     = part[mt][0];
                    red[warp_m * 32 + mt * 16 + 8 + g][warp_n] = part[mt][1];
                }
            }
            __syncthreads();
            if (tid < 128) {
                int s = t * 128 + tid;
                float sc = red[tid][0] + red[tid][1] + red[tid][2] + red[tid][3];
                sc *= (s < len) ? 1.0f : -10.0f;
                sw[tid] = sc;
            }
            __syncthreads();

            // --- online softmax: all warps compute redundantly in regs ---
            float r0 = sw[lane], r1 = sw[lane + 32];
            float r2 = sw[lane + 64], r3 = sw[lane + 96];
            float tmax = fmaxf(fmaxf(r0, r1), fmaxf(r2, r3));
#pragma unroll
            for (int o = 16; o > 0; o >>= 1)
                tmax = fmaxf(tmax, __shfl_xor_sync(0xffffffffu, tmax, o));
            float m_new = fmaxf(m_run, tmax);
            float f = expf(m_run - m_new);
            m_run = m_new;
            accp.x *= f; accp.y *= f; Z_run *= f;
            float e0 = expf(r0 - m_new), e1 = expf(r1 - m_new);
            float e2 = expf(r2 - m_new), e3 = expf(r3 - m_new);
            float z = (e0 + e1) + (e2 + e3);
#pragma unroll
            for (int o = 16; o > 0; o >>= 1)
                z += __shfl_xor_sync(0xffffffffu, z, o);
            Z_run += z;
            if (tid < 128) {
                int g4 = tid >> 5;       // row tid = lane + g4*32
                float ev = (g4 == 0) ? e0 : (g4 == 1) ? e1 : (g4 == 2) ? e2 : e3;
                sw2[tid] = ev;
            }
            __syncthreads();

            // --- pooled GEMV (half2: 2 cols per LDS, hi+lo ~fp32 exact) ---
            {
                const char* Ah = dyn + A_HI_OFF + gv_chunk * CHUNKB;
                const char* Al = dyn + A_LO_OFF + gv_chunk * CHUNKB;
#pragma unroll 8
                for (int r = 0; r < 32; r++) {
                    int row = gvg * 32 + r;
                    uint32_t off = (uint32_t)(row * 64
                                 + ((gv_unit ^ ((row >> 1) & 3)) << 4)
                                 + gv_within);
                    float2 xh = __half22float2(*(const __half2*)(Ah + off));
                    float2 xl = __half22float2(*(const __half2*)(Al + off));
                    float w = sw2[row];
                    accp.x += w * (xh.x + xl.x);
                    accp.y += w * (xh.y + xl.y);
                }
            }
            __syncthreads();              // protect A regions + sw/sw2 reuse
        }

        // --- write pooled[bn, :] ---
        accbuf[gvg][gvp] = accp;
        __syncthreads();
        if (tid < 128) {
            float2 p0 = accbuf[0][tid], p1 = accbuf[1][tid];
            float2 p2 = accbuf[2][tid], p3 = accbuf[3][tid];
            float invZ = 1.0f / Z_run;
            float2 r;
            r.x = ((p0.x + p1.x) + (p2.x + p3.x)) * invZ;
            r.y = ((p0.y + p1.y) + (p2.y + p3.y)) * invZ;
            ((float2*)(d_pooled + (long)bn * DIN))[tid] = r;
        }
        __syncthreads();
    }
#undef LOAD_ST
#undef CONV_STORE
}

// ---------------------------------------------------------------------------
// Kernel 2: gated readout
// ---------------------------------------------------------------------------
__global__ __launch_bounds__(256)
void gated_kernel(const float* __restrict__ Wa, const float* __restrict__ ba,
                  const float* __restrict__ We, const float* __restrict__ be,
                  const float* __restrict__ Wf, const float* __restrict__ bf) {
    const int b = blockIdx.x >> 3;
    const int gr = blockIdx.x & 7;
    __shared__ float P[16][DIN];
    __shared__ float AE[16][DIN];
    const int tid = threadIdx.x;

    for (int i = tid; i < 16 * DIN; i += 256) {
        int r = i >> 8;
        int d = i & 255;
        P[r][d] = d_pooled[((b * N_) + gr * 16 + r) * DIN + d];
    }
    __syncthreads();

    const int o = tid;
    for (int r = 0; r < 16; r++) {
        float sa = ba[o], se = be[o];
#pragma unroll 4
        for (int d = 0; d < DIN; d++) {
            float p = P[r][d];
            sa += p * Wa[o * DIN + d];
            se += p * We[o * DIN + d];
        }
        float att = 1.0f / (1.0f + expf(-sa));
        float emb = tanhf(se);
        AE[r][o] = att * emb;
    }
    __syncthreads();

    const int o2 = tid & 63;
    const int rg = tid >> 6;
    for (int rp = 0; rp < 4; rp++) {
        int r = rp * 4 + rg;
        float sg = bf[o2];
#pragma unroll 4
        for (int d = 0; d < DIN; d++) sg += AE[r][d] * Wf[o2 * DIN + d];
        d_g[((b * N_) + gr * 16 + r) * DOUT + o2] = sg;
    }
}

// ---------------------------------------------------------------------------
// Kernel 3: out[b,o] = sum_n g[b,n,o] / N + max_n g[b,n,o]
// ---------------------------------------------------------------------------
__global__ __launch_bounds__(256)
void final_kernel(float* __restrict__ out) {
    const int b = blockIdx.x;
    const int o = threadIdx.x & 63;
    const int g = threadIdx.x >> 6;
    __shared__ float ss[4][64], sm[4][64];

    const float* gp = d_g + ((long)(b * N_) + g * 32) * DOUT + o;
    float s = 0.f, m = -1e30f;
#pragma unroll
    for (int n = 0; n < 32; n++) {
        float v = gp[n * DOUT];
        s += v;
        m = fmaxf(m, v);
    }
    ss[g][o] = s;
    sm[g][o] = m;
    __syncthreads();
    if (threadIdx.x < 64) {
        int t = threadIdx.x;
        float S = (ss[0][t] + ss[1][t]) + (ss[2][t] + ss[3][t]);
        float M = fmaxf(fmaxf(sm[0][t], sm[1][t]), fmaxf(sm[2][t], sm[3][t]));
        out[b * DOUT + t] = S / (float)N_ + M;
    }
}

// ---------------------------------------------------------------------------
extern "C" void kernel_launch(void* const* d_in, const int* in_sizes, int n_in,
                              void* d_out, int out_size) {
    const float* x      = (const float*)d_in[0];
    const int*   seqlen = (const int*)  d_in[1];
    const float* W1     = (const float*)d_in[2];
    const float* b1     = (const float*)d_in[3];
    const float* wlen   = (const float*)d_in[4];
    const float* Wa     = (const float*)d_in[5];
    const float* ba     = (const float*)d_in[6];
    const float* We     = (const float*)d_in[7];
    const float* be     = (const float*)d_in[8];
    const float* Wf     = (const float*)d_in[9];
    const float* bf     = (const float*)d_in[10];
    float* out = (float*)d_out;

    cudaFuncSetAttribute(scorepool,
                         cudaFuncAttributeMaxDynamicSharedMemorySize, DYN_SMEM);
    scorepool<<<GRID_SC, 512, DYN_SMEM>>>(x, W1, b1, wlen, seqlen);
    gated_kernel<<<B_ * 8, 256>>>(Wa, ba, We, be, Wf, bf);
    final_kernel<<<B_, 256>>>(out);
}